// round 1
// baseline (speedup 1.0000x reference)
#include <cuda_runtime.h>
#include <cuda_bf16.h>

// ---------------- problem constants ----------------
#define NN   30          // nodes per graph
#define HH   4           // heads
#define CC   64          // channels per head
#define HC   256         // HH*CC
#define FIN  64
#define NB   1024        // graphs
#define EPG  240         // edges per graph (input)
#define NE   (NB*EPG)    // 245760 input edges
#define NL   (NB*NN)     // 30720 nodes total
#define ET   (NE+NL)     // 276480 edges incl self loops
#define EG   (EPG+NN)    // 270 edges per graph incl self loops

#define OUT_LEN   (NB*144)
#define ALPHA_OFF OUT_LEN
#define ALPHA_LEN (ET*HH)
#define EI_OFF    (ALPHA_OFF+ALPHA_LEN)
#define EI_LEN    (2*ET)

#define LN_EPS 1e-5f
#define NSLOPE 0.2f

// ---------------- device scratch (static, no allocation) ----------------
__device__ float g_WlT[FIN*HC];
__device__ float g_WrT[FIN*HC];
__device__ float g_w0t[256*3*256];   // [(cin*3+k)*256 + cout]
__device__ float g_w1t[256*3*512];
__device__ float g_w2t[512*3*256];
__device__ float g_d1t[256*512];     // [cin*512 + cout]
__device__ float g_d2t[512*256];
__device__ float g_xl[NL*HC];
__device__ float g_xr[NL*HC];
__device__ float g_h [NB*HC*NN];     // [b][c][l]
__device__ float g_z [NB*HC*NN];     // TCN output, [b][c*30+l]
__device__ float g_z1[NB*512];
__device__ float g_z2[NB*256];

// ---------------- weight transposes ----------------
__global__ void prep_kernel(const float* __restrict__ Wl, const float* __restrict__ Wr,
                            const float* __restrict__ w0, const float* __restrict__ w1,
                            const float* __restrict__ w2, const float* __restrict__ d1,
                            const float* __restrict__ d2)
{
    int t0 = blockIdx.x*blockDim.x + threadIdx.x;
    int stride = gridDim.x*blockDim.x;
    for (int i=t0;i<FIN*HC;i+=stride){ int j=i%HC,k=i/HC; g_WlT[i]=Wl[j*FIN+k]; g_WrT[i]=Wr[j*FIN+k]; }
    for (int i=t0;i<256*3*256;i+=stride){ int c=i%256,r=i/256; int k=r%3,cin=r/3; g_w0t[i]=w0[(c*256+cin)*3+k]; }
    for (int i=t0;i<256*3*512;i+=stride){ int c=i%512,r=i/512; int k=r%3,cin=r/3; g_w1t[i]=w1[(c*256+cin)*3+k]; }
    for (int i=t0;i<512*3*256;i+=stride){ int c=i%256,r=i/256; int k=r%3,cin=r/3; g_w2t[i]=w2[(c*512+cin)*3+k]; }
    for (int i=t0;i<256*512;i+=stride){ int c=i%512,cin=i/512; g_d1t[i]=d1[c*256+cin]; }
    for (int i=t0;i<512*256;i+=stride){ int c=i%256,cin=i/256; g_d2t[i]=d2[c*512+cin]; }
}

// ---------------- xl = x@Wl^T+bl, xr = x@Wr^T+br ----------------
__global__ void __launch_bounds__(256) xform_kernel(const float* __restrict__ x,
                                                    const float* __restrict__ bl,
                                                    const float* __restrict__ br)
{
    __shared__ float xs[32*FIN];
    const int base = blockIdx.x*32;
    const int tid = threadIdx.x;
    for (int i=tid;i<32*FIN;i+=256) xs[i]=x[base*FIN+i];
    __syncthreads();
    float accl[32], accr[32];
#pragma unroll
    for (int n=0;n<32;n++){ accl[n]=0.f; accr[n]=0.f; }
    const int j = tid;
    for (int k=0;k<FIN;k++){
        float wl=g_WlT[k*HC+j], wr=g_WrT[k*HC+j];
#pragma unroll
        for (int n=0;n<32;n++){ float xv=xs[n*FIN+k]; accl[n]=fmaf(wl,xv,accl[n]); accr[n]=fmaf(wr,xv,accr[n]); }
    }
    float blv=bl[j], brv=br[j];
#pragma unroll
    for (int n=0;n<32;n++){
        g_xl[(base+n)*HC+j]=accl[n]+blv;
        g_xr[(base+n)*HC+j]=accr[n]+brv;
    }
}

// ---------------- GATv2 attention: one CTA per graph ----------------
// dyn smem layout (floats then ints)
#define ATTN_SMEM_BYTES (18272*4 + 901*4 + 16)

__global__ void __launch_bounds__(256) attn_kernel(const int* __restrict__ eidx,
                                                   const float* __restrict__ att,
                                                   const float* __restrict__ gbias,
                                                   float* __restrict__ out,
                                                   int write_alpha)
{
    extern __shared__ char smemraw[];
    float* xl_s   = (float*)smemraw;        // 7680
    float* xr_s   = xl_s + 7680;            // 7680 (reused as output stage)
    float* att_s  = xr_s + 7680;            // 256
    float* bias_s = att_s + 256;            // 256
    float* esc    = bias_s + 256;           // 1080
    float* alp    = esc + 1080;             // 1080
    float* mmax   = alp + 1080;             // 120
    float* ssum   = mmax + 120;             // 120
    int*   srcl   = (int*)(ssum + 120);     // 270
    int*   dstl   = srcl + 270;             // 270
    int*   deg    = dstl + 270;             // 30
    int*   off    = deg + 30;               // 31
    int*   pos    = off + 31;               // 30
    int*   order  = pos + 30;               // 270

    const int b = blockIdx.x, tid = threadIdx.x;

    for (int i=tid;i<7680;i+=256){ xl_s[i]=g_xl[b*7680+i]; xr_s[i]=g_xr[b*7680+i]; }
    for (int i=tid;i<256;i+=256){ att_s[i]=att[i]; bias_s[i]=gbias[i]; }
    if (tid<30) deg[tid]=0;
    __syncthreads();

    // edges + degree count
    for (int e=tid;e<EG;e+=256){
        int s,d;
        if (e<EPG){ s=eidx[b*EPG+e]-b*NN; d=eidx[NE+b*EPG+e]-b*NN; }
        else      { s=e-EPG; d=e-EPG; }
        srcl[e]=s; dstl[e]=d;
        atomicAdd(&deg[d],1);
    }
    __syncthreads();
    if (tid==0){ off[0]=0; for (int n=0;n<NN;n++) off[n+1]=off[n]+deg[n]; }
    __syncthreads();
    if (tid<30) pos[tid]=off[tid];
    __syncthreads();
    for (int e=tid;e<EG;e+=256){ int slot=atomicAdd(&pos[dstl[e]],1); order[slot]=e; }
    __syncthreads();

    // scores e[e][h]
    for (int idx=tid; idx<EG*HH; idx+=256){
        int e=idx>>2, h=idx&3;
        const float* ps=&xl_s[srcl[e]*HC + h*CC];
        const float* pd=&xr_s[dstl[e]*HC + h*CC];
        const float* pa=&att_s[h*CC];
        float acc=0.f;
#pragma unroll 8
        for (int c=0;c<CC;c++){
            float v=ps[c]+pd[c];
            v = v>0.f ? v : NSLOPE*v;
            acc = fmaf(v, pa[c], acc);
        }
        esc[e*HH+h]=acc;
    }
    __syncthreads();

    // segment softmax stats per (node, head)
    for (int idx=tid; idx<NN*HH; idx+=256){
        int n=idx>>2, h=idx&3;
        float m=-1e30f;
        for (int i=off[n];i<off[n+1];i++) m=fmaxf(m, esc[order[i]*HH+h]);
        float s=0.f;
        for (int i=off[n];i<off[n+1];i++) s+=__expf(esc[order[i]*HH+h]-m);
        mmax[idx]=m; ssum[idx]=s;
    }
    __syncthreads();

    // alpha
    for (int idx=tid; idx<EG*HH; idx+=256){
        int e=idx>>2, h=idx&3;
        int d=dstl[e];
        float a=__expf(esc[e*HH+h]-mmax[d*HH+h])/ssum[d*HH+h];
        alp[e*HH+h]=a;
        if (write_alpha){
            int gid = (e<EPG) ? (b*EPG+e) : (NE + b*NN + (e-EPG));
            out[ALPHA_OFF + gid*HH + h]=a;
        }
    }
    __syncthreads();

    // aggregate + bias + relu, staged into xr_s[j*30+n]
    {
        const int j = tid;
        const int h = j>>6;
        for (int n=0;n<NN;n++){
            float acc=0.f;
            for (int i=off[n];i<off[n+1];i++){
                int e=order[i];
                acc = fmaf(alp[e*HH+h], xl_s[srcl[e]*HC+j], acc);
            }
            float v=acc+bias_s[j];
            xr_s[j*NN+n]=fmaxf(v,0.f);
        }
    }
    __syncthreads();
    for (int i=tid;i<7680;i+=256) g_h[b*7680+i]=xr_s[i];
}

// ---------------- TCN: one CTA per graph, activations in shared ----------------
#define TCN_SMEM_BYTES (30720*4)

__global__ void __launch_bounds__(256) tcn_kernel(const float* __restrict__ b0,
    const float* __restrict__ ln0w, const float* __restrict__ ln0b,
    const float* __restrict__ b1, const float* __restrict__ ln1w, const float* __restrict__ ln1b,
    const float* __restrict__ db1,
    const float* __restrict__ b2, const float* __restrict__ ln2w, const float* __restrict__ ln2b,
    const float* __restrict__ db2)
{
    extern __shared__ float sm[];
    float* shA = sm;            // 7680  (h, later output stage)
    float* shB = sm + 7680;     // 7680  (y0)
    float* shC = sm + 15360;    // 15360 (y1, 512 ch)
    const int b = blockIdx.x, tid = threadIdx.x;

    for (int i=tid;i<7680;i+=256) shA[i]=g_h[b*7680+i];
    __syncthreads();

    // ---- layer 0: conv k3 d1 + LN + relu + residual(h) -> shB
    {
        const int c = tid;
        float acc[NN];
        float bb=b0[c];
#pragma unroll
        for (int l=0;l<NN;l++) acc[l]=bb;
        for (int cin=0;cin<256;cin++){
            const float* hp=&shA[cin*NN];
            float hr[NN];
#pragma unroll
            for (int l=0;l<NN;l++) hr[l]=hp[l];
            const float* wp=&g_w0t[cin*3*256 + c];
            float w0=wp[0], w1=wp[256], w2=wp[512];
#pragma unroll
            for (int l=0;l<NN;l++){
                float s=w1*hr[l];
                if (l>0)   s=fmaf(w0,hr[l-1],s);
                if (l<NN-1)s=fmaf(w2,hr[l+1],s);
                acc[l]+=s;
            }
        }
        float mean=0.f;
#pragma unroll
        for (int l=0;l<NN;l++) mean+=acc[l];
        mean*= (1.f/NN);
        float var=0.f;
#pragma unroll
        for (int l=0;l<NN;l++){ float d=acc[l]-mean; var=fmaf(d,d,var); }
        var*=(1.f/NN);
        float rs=rsqrtf(var+LN_EPS);
#pragma unroll
        for (int l=0;l<NN;l++){
            float v=(acc[l]-mean)*rs*__ldg(&ln0w[l])+__ldg(&ln0b[l]);
            v=fmaxf(v,0.f);
            shB[c*NN+l]=v+shA[c*NN+l];
        }
    }
    __syncthreads();

    // ---- layer 1: conv k3 d2 (512ch) + LN + relu + ds1 -> shC
    for (int half=0; half<2; half++){
        const int c = tid + half*256;
        float acc[NN], ad[NN];
        float bb=b1[c], bd=db1[c];
#pragma unroll
        for (int l=0;l<NN;l++){ acc[l]=bb; ad[l]=bd; }
        for (int cin=0;cin<256;cin++){
            const float* hp=&shB[cin*NN];
            float hr[NN];
#pragma unroll
            for (int l=0;l<NN;l++) hr[l]=hp[l];
            const float* wp=&g_w1t[cin*3*512 + c];
            float w0=wp[0], w1=wp[512], w2=wp[1024];
            float wd=g_d1t[cin*512 + c];
#pragma unroll
            for (int l=0;l<NN;l++){
                float s=w1*hr[l];
                if (l>=2)   s=fmaf(w0,hr[l-2],s);
                if (l<NN-2) s=fmaf(w2,hr[l+2],s);
                acc[l]+=s;
                ad[l]=fmaf(wd,hr[l],ad[l]);
            }
        }
        float mean=0.f;
#pragma unroll
        for (int l=0;l<NN;l++) mean+=acc[l];
        mean*=(1.f/NN);
        float var=0.f;
#pragma unroll
        for (int l=0;l<NN;l++){ float d=acc[l]-mean; var=fmaf(d,d,var); }
        var*=(1.f/NN);
        float rs=rsqrtf(var+LN_EPS);
#pragma unroll
        for (int l=0;l<NN;l++){
            float v=(acc[l]-mean)*rs*__ldg(&ln1w[l])+__ldg(&ln1b[l]);
            v=fmaxf(v,0.f);
            shC[c*NN+l]=v+ad[l];
        }
    }
    __syncthreads();

    // ---- layer 2: conv k3 d4 (256 out, 512 in) + LN + relu + ds2 -> shA stage
    {
        const int c = tid;
        float acc[NN], ad[NN];
        float bb=b2[c], bd=db2[c];
#pragma unroll
        for (int l=0;l<NN;l++){ acc[l]=bb; ad[l]=bd; }
        for (int cin=0;cin<512;cin++){
            const float* hp=&shC[cin*NN];
            float hr[NN];
#pragma unroll
            for (int l=0;l<NN;l++) hr[l]=hp[l];
            const float* wp=&g_w2t[cin*3*256 + c];
            float w0=wp[0], w1=wp[256], w2=wp[512];
            float wd=g_d2t[cin*256 + c];
#pragma unroll
            for (int l=0;l<NN;l++){
                float s=w1*hr[l];
                if (l>=4)   s=fmaf(w0,hr[l-4],s);
                if (l<NN-4) s=fmaf(w2,hr[l+4],s);
                acc[l]+=s;
                ad[l]=fmaf(wd,hr[l],ad[l]);
            }
        }
        float mean=0.f;
#pragma unroll
        for (int l=0;l<NN;l++) mean+=acc[l];
        mean*=(1.f/NN);
        float var=0.f;
#pragma unroll
        for (int l=0;l<NN;l++){ float d=acc[l]-mean; var=fmaf(d,d,var); }
        var*=(1.f/NN);
        float rs=rsqrtf(var+LN_EPS);
#pragma unroll
        for (int l=0;l<NN;l++){
            float v=(acc[l]-mean)*rs*__ldg(&ln2w[l])+__ldg(&ln2b[l]);
            v=fmaxf(v,0.f);
            shA[c*NN+l]=v+ad[l];
        }
    }
    __syncthreads();
    for (int i=tid;i<7680;i+=256) g_z[b*7680+i]=shA[i];
}

// ---------------- tiled SGEMM: C[M,N] = act(A[M,K] @ W[N,K]^T + bias) ----------------
__global__ void __launch_bounds__(256) gemm_kernel(const float* __restrict__ A,
                                                   const float* __restrict__ W,
                                                   const float* __restrict__ bias,
                                                   float* __restrict__ C,
                                                   int M, int N, int K, int relu)
{
    __shared__ float sA[64][17];
    __shared__ float sW[64][17];
    const int tid=threadIdx.x;
    const int m0=blockIdx.y*64, n0=blockIdx.x*64;
    const int tr=(tid/16)*4, tc=(tid%16)*4;
    float acc[4][4];
#pragma unroll
    for (int i=0;i<4;i++)
#pragma unroll
        for (int j=0;j<4;j++) acc[i][j]=0.f;

    for (int k0=0;k0<K;k0+=16){
        for (int i=tid;i<1024;i+=256){
            int k=i&15, r=i>>4;
            int gm=m0+r, gk=k0+k;
            sA[r][k]=(gm<M && gk<K)? A[gm*K+gk] : 0.f;
            int gn=n0+r;
            sW[r][k]=(gn<N && gk<K)? W[gn*K+gk] : 0.f;
        }
        __syncthreads();
#pragma unroll
        for (int k=0;k<16;k++){
            float a[4], w[4];
#pragma unroll
            for (int i=0;i<4;i++) a[i]=sA[tr+i][k];
#pragma unroll
            for (int j=0;j<4;j++) w[j]=sW[tc+j][k];
#pragma unroll
            for (int i=0;i<4;i++)
#pragma unroll
                for (int j=0;j<4;j++) acc[i][j]=fmaf(a[i],w[j],acc[i][j]);
        }
        __syncthreads();
    }
#pragma unroll
    for (int i=0;i<4;i++){
        int gm=m0+tr+i;
        if (gm>=M) continue;
#pragma unroll
        for (int j=0;j<4;j++){
            int gn=n0+tc+j;
            if (gn>=N) continue;
            float v=acc[i][j]+bias[gn];
            if (relu) v=fmaxf(v,0.f);
            C[gm*N+gn]=v;
        }
    }
}

// ---------------- ei output ----------------
__global__ void ei_kernel(const int* __restrict__ eidx, float* __restrict__ out)
{
    int e=blockIdx.x*blockDim.x+threadIdx.x;
    if (e>=ET) return;
    int s,d;
    if (e<NE){ s=eidx[e]; d=eidx[NE+e]; }
    else { s=e-NE; d=e-NE; }
    out[EI_OFF+e]      =(float)s;
    out[EI_OFF+ET+e]   =(float)d;
}

// ---------------- launch ----------------
extern "C" void kernel_launch(void* const* d_in, const int* in_sizes, int n_in,
                              void* d_out, int out_size)
{
    const float* x      =(const float*)d_in[0];
    const float* gat_Wl =(const float*)d_in[1];
    const float* gat_bl =(const float*)d_in[2];
    const float* gat_Wr =(const float*)d_in[3];
    const float* gat_br =(const float*)d_in[4];
    const float* gat_att=(const float*)d_in[5];
    const float* gat_bias=(const float*)d_in[6];
    const float* tcn0_w =(const float*)d_in[7];
    const float* tcn0_b =(const float*)d_in[8];
    const float* ln0_w  =(const float*)d_in[9];
    const float* ln0_b  =(const float*)d_in[10];
    const float* tcn1_w =(const float*)d_in[11];
    const float* tcn1_b =(const float*)d_in[12];
    const float* ln1_w  =(const float*)d_in[13];
    const float* ln1_b  =(const float*)d_in[14];
    const float* ds1_w  =(const float*)d_in[15];
    const float* ds1_b  =(const float*)d_in[16];
    const float* tcn2_w =(const float*)d_in[17];
    const float* tcn2_b =(const float*)d_in[18];
    const float* ln2_w  =(const float*)d_in[19];
    const float* ln2_b  =(const float*)d_in[20];
    const float* ds2_w  =(const float*)d_in[21];
    const float* ds2_b  =(const float*)d_in[22];
    const float* fc1_w  =(const float*)d_in[23];
    const float* fc1_b  =(const float*)d_in[24];
    const float* fc2_w  =(const float*)d_in[25];
    const float* fc2_b  =(const float*)d_in[26];
    const float* fc3_w  =(const float*)d_in[27];
    const float* fc3_b  =(const float*)d_in[28];
    const int*   edge   =(const int*)d_in[29];
    float* out=(float*)d_out;

    cudaFuncSetAttribute(attn_kernel, cudaFuncAttributeMaxDynamicSharedMemorySize, ATTN_SMEM_BYTES);
    cudaFuncSetAttribute(tcn_kernel,  cudaFuncAttributeMaxDynamicSharedMemorySize, TCN_SMEM_BYTES);

    prep_kernel<<<512,256>>>(gat_Wl, gat_Wr, tcn0_w, tcn1_w, tcn2_w, ds1_w, ds2_w);
    xform_kernel<<<NL/32,256>>>(x, gat_bl, gat_br);

    int write_alpha = (out_size >= ALPHA_OFF + ALPHA_LEN) ? 1 : 0;
    attn_kernel<<<NB,256,ATTN_SMEM_BYTES>>>(edge, gat_att, gat_bias, out, write_alpha);

    tcn_kernel<<<NB,256,TCN_SMEM_BYTES>>>(tcn0_b, ln0_w, ln0_b,
                                          tcn1_b, ln1_w, ln1_b, ds1_b,
                                          tcn2_b, ln2_w, ln2_b, ds2_b);

    void *pz=nullptr,*pz1=nullptr,*pz2=nullptr;
    cudaGetSymbolAddress(&pz,  g_z);
    cudaGetSymbolAddress(&pz1, g_z1);
    cudaGetSymbolAddress(&pz2, g_z2);

    gemm_kernel<<<dim3(512/64, NB/64),256>>>((const float*)pz,  fc1_w, fc1_b, (float*)pz1, NB, 512, 7680, 1);
    gemm_kernel<<<dim3(256/64, NB/64),256>>>((const float*)pz1, fc2_w, fc2_b, (float*)pz2, NB, 256, 512, 1);
    gemm_kernel<<<dim3((144+63)/64, NB/64),256>>>((const float*)pz2, fc3_w, fc3_b, out, NB, 144, 256, 0);

    if (out_size >= EI_OFF + EI_LEN)
        ei_kernel<<<(ET+255)/256,256>>>(edge, out);
}

// round 2
// speedup vs baseline: 1.4874x; 1.4874x over previous
#include <cuda_runtime.h>
#include <cuda_bf16.h>

// ---------------- problem constants ----------------
#define NN   30          // nodes per graph
#define HH   4           // heads
#define CC   64          // channels per head
#define HC   256         // HH*CC
#define FIN  64
#define NB   1024        // graphs
#define EPG  240         // edges per graph (input)
#define NE   (NB*EPG)    // 245760 input edges
#define NL   (NB*NN)     // 30720 nodes total
#define ET   (NE+NL)     // 276480 edges incl self loops
#define EG   (EPG+NN)    // 270 edges per graph incl self loops

#define OUT_LEN   (NB*144)
#define ALPHA_OFF OUT_LEN
#define ALPHA_LEN (ET*HH)
#define EI_OFF    (ALPHA_OFF+ALPHA_LEN)
#define EI_LEN    (2*ET)

#define LN_EPS 1e-5f
#define NSLOPE 0.2f

// padded activation row: [4 zero][30 data][6 zero] = 40 floats
#define RS 40

typedef unsigned long long u64;

__device__ __forceinline__ u64 pk2(float a, float b){
    u64 r; asm("mov.b64 %0,{%1,%2};":"=l"(r):"f"(a),"f"(b)); return r;
}
__device__ __forceinline__ u64 f2fma(u64 a, u64 b, u64 c){
    u64 d; asm("fma.rn.f32x2 %0,%1,%2,%3;":"=l"(d):"l"(a),"l"(b),"l"(c)); return d;
}
__device__ __forceinline__ void upk(u64 v, float& lo, float& hi){
    asm("mov.b64 {%0,%1},%2;":"=f"(lo),"=f"(hi):"l"(v));
}

// ---------------- device scratch (static, no allocation) ----------------
__device__ float g_WlT[FIN*HC];
__device__ float g_WrT[FIN*HC];
__device__ float g_w0t[256*3*256];   // [(cin*3+k)*256 + cout]
__device__ float g_w1t[256*3*512];
__device__ float g_w2t[512*3*256];
__device__ float g_d1t[256*512];     // [cin*512 + cout]
__device__ float g_d2t[512*256];
__device__ float g_xl[NL*HC];
__device__ float g_xr[NL*HC];
__device__ float g_h [NB*HC*NN];        // attn output [b][c][l] stride 30
__device__ float g_y0[NB*256*RS];       // layer0 out, padded rows
__device__ float g_y1[NB*512*RS];       // layer1 out, padded rows
__device__ float g_z [NB*HC*NN];        // TCN output [b][c*30+l]
__device__ float g_z1[NB*512];
__device__ float g_z2[NB*256];

// ---------------- weight transposes ----------------
__global__ void prep_kernel(const float* __restrict__ Wl, const float* __restrict__ Wr,
                            const float* __restrict__ w0, const float* __restrict__ w1,
                            const float* __restrict__ w2, const float* __restrict__ d1,
                            const float* __restrict__ d2)
{
    int t0 = blockIdx.x*blockDim.x + threadIdx.x;
    int stride = gridDim.x*blockDim.x;
    for (int i=t0;i<FIN*HC;i+=stride){ int j=i%HC,k=i/HC; g_WlT[i]=Wl[j*FIN+k]; g_WrT[i]=Wr[j*FIN+k]; }
    for (int i=t0;i<256*3*256;i+=stride){ int c=i%256,r=i/256; int k=r%3,cin=r/3; g_w0t[i]=w0[(c*256+cin)*3+k]; }
    for (int i=t0;i<256*3*512;i+=stride){ int c=i%512,r=i/512; int k=r%3,cin=r/3; g_w1t[i]=w1[(c*256+cin)*3+k]; }
    for (int i=t0;i<512*3*256;i+=stride){ int c=i%256,r=i/256; int k=r%3,cin=r/3; g_w2t[i]=w2[(c*512+cin)*3+k]; }
    for (int i=t0;i<256*512;i+=stride){ int c=i%512,cin=i/512; g_d1t[i]=d1[c*256+cin]; }
    for (int i=t0;i<512*256;i+=stride){ int c=i%256,cin=i/256; g_d2t[i]=d2[c*512+cin]; }
}

// ---------------- xl = x@Wl^T+bl, xr = x@Wr^T+br ----------------
__global__ void __launch_bounds__(256) xform_kernel(const float* __restrict__ x,
                                                    const float* __restrict__ bl,
                                                    const float* __restrict__ br)
{
    __shared__ float xs[32*FIN];
    const int base = blockIdx.x*32;
    const int tid = threadIdx.x;
    for (int i=tid;i<32*FIN;i+=256) xs[i]=x[base*FIN+i];
    __syncthreads();
    float accl[32], accr[32];
#pragma unroll
    for (int n=0;n<32;n++){ accl[n]=0.f; accr[n]=0.f; }
    const int j = tid;
    for (int k=0;k<FIN;k++){
        float wl=g_WlT[k*HC+j], wr=g_WrT[k*HC+j];
#pragma unroll
        for (int n=0;n<32;n++){ float xv=xs[n*FIN+k]; accl[n]=fmaf(wl,xv,accl[n]); accr[n]=fmaf(wr,xv,accr[n]); }
    }
    float blv=bl[j], brv=br[j];
#pragma unroll
    for (int n=0;n<32;n++){
        g_xl[(base+n)*HC+j]=accl[n]+blv;
        g_xr[(base+n)*HC+j]=accr[n]+brv;
    }
}

// ---------------- GATv2 attention: one CTA per graph ----------------
#define ATTN_SMEM_BYTES (18272*4 + 901*4 + 16)

__global__ void __launch_bounds__(256) attn_kernel(const int* __restrict__ eidx,
                                                   const float* __restrict__ att,
                                                   const float* __restrict__ gbias,
                                                   float* __restrict__ out,
                                                   int write_alpha)
{
    extern __shared__ char smemraw[];
    float* xl_s   = (float*)smemraw;        // 7680
    float* xr_s   = xl_s + 7680;            // 7680 (reused as output stage)
    float* att_s  = xr_s + 7680;            // 256
    float* bias_s = att_s + 256;            // 256
    float* esc    = bias_s + 256;           // 1080
    float* alp    = esc + 1080;             // 1080
    float* mmax   = alp + 1080;             // 120
    float* ssum   = mmax + 120;             // 120
    int*   srcl   = (int*)(ssum + 120);     // 270
    int*   dstl   = srcl + 270;             // 270
    int*   deg    = dstl + 270;             // 30
    int*   off    = deg + 30;               // 31
    int*   pos    = off + 31;               // 30
    int*   order  = pos + 30;               // 270

    const int b = blockIdx.x, tid = threadIdx.x;

    for (int i=tid;i<7680;i+=256){ xl_s[i]=g_xl[b*7680+i]; xr_s[i]=g_xr[b*7680+i]; }
    for (int i=tid;i<256;i+=256){ att_s[i]=att[i]; bias_s[i]=gbias[i]; }
    if (tid<30) deg[tid]=0;
    __syncthreads();

    for (int e=tid;e<EG;e+=256){
        int s,d;
        if (e<EPG){ s=eidx[b*EPG+e]-b*NN; d=eidx[NE+b*EPG+e]-b*NN; }
        else      { s=e-EPG; d=e-EPG; }
        srcl[e]=s; dstl[e]=d;
        atomicAdd(&deg[d],1);
    }
    __syncthreads();
    if (tid==0){ off[0]=0; for (int n=0;n<NN;n++) off[n+1]=off[n]+deg[n]; }
    __syncthreads();
    if (tid<30) pos[tid]=off[tid];
    __syncthreads();
    for (int e=tid;e<EG;e+=256){ int slot=atomicAdd(&pos[dstl[e]],1); order[slot]=e; }
    __syncthreads();

    for (int idx=tid; idx<EG*HH; idx+=256){
        int e=idx>>2, h=idx&3;
        const float* ps=&xl_s[srcl[e]*HC + h*CC];
        const float* pd=&xr_s[dstl[e]*HC + h*CC];
        const float* pa=&att_s[h*CC];
        float acc=0.f;
#pragma unroll 8
        for (int c=0;c<CC;c++){
            float v=ps[c]+pd[c];
            v = v>0.f ? v : NSLOPE*v;
            acc = fmaf(v, pa[c], acc);
        }
        esc[e*HH+h]=acc;
    }
    __syncthreads();

    for (int idx=tid; idx<NN*HH; idx+=256){
        int n=idx>>2, h=idx&3;
        float m=-1e30f;
        for (int i=off[n];i<off[n+1];i++) m=fmaxf(m, esc[order[i]*HH+h]);
        float s=0.f;
        for (int i=off[n];i<off[n+1];i++) s+=__expf(esc[order[i]*HH+h]-m);
        mmax[idx]=m; ssum[idx]=s;
    }
    __syncthreads();

    for (int idx=tid; idx<EG*HH; idx+=256){
        int e=idx>>2, h=idx&3;
        int d=dstl[e];
        float a=__expf(esc[e*HH+h]-mmax[d*HH+h])/ssum[d*HH+h];
        alp[e*HH+h]=a;
        if (write_alpha){
            int gid = (e<EPG) ? (b*EPG+e) : (NE + b*NN + (e-EPG));
            out[ALPHA_OFF + gid*HH + h]=a;
        }
    }
    __syncthreads();

    {
        const int j = tid;
        const int h = j>>6;
        for (int n=0;n<NN;n++){
            float acc=0.f;
            for (int i=off[n];i<off[n+1];i++){
                int e=order[i];
                acc = fmaf(alp[e*HH+h], xl_s[srcl[e]*HC+j], acc);
            }
            float v=acc+bias_s[j];
            xr_s[j*NN+n]=fmaxf(v,0.f);
        }
    }
    __syncthreads();
    for (int i=tid;i<7680;i+=256) g_h[b*7680+i]=xr_s[i];
}

// ================= TCN layer 0: conv k3 d1 + LN + relu + residual =================
// smem: base copy (256*RS) + shifted copy (256*RS) = 80KB
#define L0_SMEM (2*256*RS*4)
__global__ void __launch_bounds__(256,2) tcn0_kernel(const float* __restrict__ b0,
    const float* __restrict__ ln0w, const float* __restrict__ ln0b)
{
    extern __shared__ float sm[];
    float* base = sm;             // 256*RS
    float* cp2  = sm + 256*RS;    // 256*RS, data at +5
    const int b = blockIdx.x, tid = threadIdx.x;

    for (int i=tid;i<2*256*RS;i+=256) sm[i]=0.f;
    __syncthreads();
    for (int i=tid;i<7680;i+=256){
        int c=i/NN, l=i-c*NN;
        float v=g_h[b*7680+i];
        base[c*RS+4+l]=v; cp2[c*RS+5+l]=v;
    }
    __syncthreads();

    const int c = tid;
    u64 acc[15];
    {
        float bb=b0[c]; u64 bp=pk2(bb,bb);
#pragma unroll
        for (int i=0;i<15;i++) acc[i]=bp;
    }
    for (int cin=0;cin<256;cin++){
        const float* r =&base[cin*RS];
        const float* r2=&cp2 [cin*RS];
        const float* wp=&g_w0t[cin*768 + c];
        float w0=wp[0], w1=wp[256], w2=wp[512];
        u64 w0p=pk2(w0,w0), w1p=pk2(w1,w1), w2p=pk2(w2,w2);
        u64 cp[16];
#pragma unroll
        for (int j=0;j<16;j++) cp[j]=*(const u64*)(r2+4+2*j);  // pair start 2j-1
#pragma unroll
        for (int i=0;i<15;i++){
            u64 bp=*(const u64*)(r+4+2*i);                      // pair start 2i
            acc[i]=f2fma(w1p,bp,acc[i]);
            acc[i]=f2fma(w0p,cp[i],acc[i]);     // h[2i-1],h[2i]
            acc[i]=f2fma(w2p,cp[i+1],acc[i]);   // h[2i+1],h[2i+2]
        }
    }
    float a[30];
#pragma unroll
    for (int i=0;i<15;i++) upk(acc[i], a[2*i], a[2*i+1]);
    float mean=0.f;
#pragma unroll
    for (int l=0;l<NN;l++) mean+=a[l];
    mean*=(1.f/NN);
    float var=0.f;
#pragma unroll
    for (int l=0;l<NN;l++){ float d=a[l]-mean; var=fmaf(d,d,var); }
    var*=(1.f/NN);
    float rs=rsqrtf(var+LN_EPS);
    float outv[30];
#pragma unroll
    for (int l=0;l<NN;l++){
        float v=(a[l]-mean)*rs*__ldg(&ln0w[l])+__ldg(&ln0b[l]);
        v=fmaxf(v,0.f);
        outv[l]=v + base[c*RS+4+l];
    }
    __syncthreads();   // all compute reads done
#pragma unroll
    for (int l=0;l<NN;l++) base[c*RS+4+l]=outv[l];   // pads remain zero
    __syncthreads();
    for (int i=tid;i<256*RS;i+=256) g_y0[b*256*RS+i]=base[i];
}

// ================= TCN layer 1: conv k3 d2 (512 out) + LN + relu + ds1 =================
// smem: input (256*RS) + stage (256*RS) = 80KB
#define L1_SMEM (2*256*RS*4)
__global__ void __launch_bounds__(256,2) tcn1_kernel(const float* __restrict__ b1,
    const float* __restrict__ ln1w, const float* __restrict__ ln1b,
    const float* __restrict__ db1)
{
    extern __shared__ float sm[];
    float* base  = sm;            // 256*RS
    float* stage = sm + 256*RS;   // 256*RS
    const int b = blockIdx.x, tid = threadIdx.x;

    for (int i=tid;i<256*RS;i+=256){ base[i]=g_y0[b*256*RS+i]; stage[i]=0.f; }
    __syncthreads();

    for (int pass=0;pass<2;pass++){
        const int c = tid + pass*256;
        u64 acc[15], ad[15];
        {
            float bb=b1[c], bd=db1[c];
            u64 p1=pk2(bb,bb), p2=pk2(bd,bd);
#pragma unroll
            for (int i=0;i<15;i++){ acc[i]=p1; ad[i]=p2; }
        }
        for (int cin=0;cin<256;cin++){
            const float* r=&base[cin*RS];
            const float* wp=&g_w1t[cin*1536 + c];
            float w0=wp[0], w1=wp[512], w2=wp[1024];
            float wd=g_d1t[cin*512 + c];
            u64 w0p=pk2(w0,w0), w1p=pk2(w1,w1), w2p=pk2(w2,w2), wdp=pk2(wd,wd);
            u64 bp[17];
#pragma unroll
            for (int j=0;j<17;j++) bp[j]=*(const u64*)(r+2+2*j);  // pair start 2(j-1)
#pragma unroll
            for (int i=0;i<15;i++){
                acc[i]=f2fma(w0p,bp[i],  acc[i]);   // start 2i-2
                acc[i]=f2fma(w1p,bp[i+1],acc[i]);   // start 2i
                acc[i]=f2fma(w2p,bp[i+2],acc[i]);   // start 2i+2
                ad [i]=f2fma(wdp,bp[i+1],ad [i]);
            }
        }
        float a[30], d[30];
#pragma unroll
        for (int i=0;i<15;i++){ upk(acc[i],a[2*i],a[2*i+1]); upk(ad[i],d[2*i],d[2*i+1]); }
        float mean=0.f;
#pragma unroll
        for (int l=0;l<NN;l++) mean+=a[l];
        mean*=(1.f/NN);
        float var=0.f;
#pragma unroll
        for (int l=0;l<NN;l++){ float t=a[l]-mean; var=fmaf(t,t,var); }
        var*=(1.f/NN);
        float rsn=rsqrtf(var+LN_EPS);
#pragma unroll
        for (int l=0;l<NN;l++){
            float v=(a[l]-mean)*rsn*__ldg(&ln1w[l])+__ldg(&ln1b[l]);
            v=fmaxf(v,0.f);
            stage[tid*RS+4+l]=v+d[l];
        }
        __syncthreads();
        for (int i=tid;i<256*RS;i+=256) g_y1[b*512*RS + pass*256*RS + i]=stage[i];
        __syncthreads();
    }
}

// ================= TCN layer 2: conv k3 d4 (256 out, 512 in) + LN + relu + ds2 =================
// smem: input 512*RS = 80KB (output staged into front of it after compute)
#define L2_SMEM (512*RS*4)
__global__ void __launch_bounds__(256,2) tcn2_kernel(const float* __restrict__ b2,
    const float* __restrict__ ln2w, const float* __restrict__ ln2b,
    const float* __restrict__ db2)
{
    extern __shared__ float sm[];
    float* base = sm;    // 512*RS
    const int b = blockIdx.x, tid = threadIdx.x;

    for (int i=tid;i<512*RS;i+=256) base[i]=g_y1[b*512*RS+i];
    __syncthreads();

    const int c = tid;
    u64 acc[15], ad[15];
    {
        float bb=b2[c], bd=db2[c];
        u64 p1=pk2(bb,bb), p2=pk2(bd,bd);
#pragma unroll
        for (int i=0;i<15;i++){ acc[i]=p1; ad[i]=p2; }
    }
    for (int cin=0;cin<512;cin++){
        const float* r=&base[cin*RS];
        const float* wp=&g_w2t[cin*768 + c];
        float w0=wp[0], w1=wp[256], w2=wp[512];
        float wd=g_d2t[cin*256 + c];
        u64 w0p=pk2(w0,w0), w1p=pk2(w1,w1), w2p=pk2(w2,w2), wdp=pk2(wd,wd);
        u64 bp[19];
#pragma unroll
        for (int j=0;j<19;j++) bp[j]=*(const u64*)(r+2*j);      // pair start 2(j-2)
#pragma unroll
        for (int i=0;i<15;i++){
            acc[i]=f2fma(w0p,bp[i],  acc[i]);   // start 2i-4
            acc[i]=f2fma(w1p,bp[i+2],acc[i]);   // start 2i
            acc[i]=f2fma(w2p,bp[i+4],acc[i]);   // start 2i+4
            ad [i]=f2fma(wdp,bp[i+2],ad [i]);
        }
    }
    float a[30], d[30];
#pragma unroll
    for (int i=0;i<15;i++){ upk(acc[i],a[2*i],a[2*i+1]); upk(ad[i],d[2*i],d[2*i+1]); }
    float mean=0.f;
#pragma unroll
    for (int l=0;l<NN;l++) mean+=a[l];
    mean*=(1.f/NN);
    float var=0.f;
#pragma unroll
    for (int l=0;l<NN;l++){ float t=a[l]-mean; var=fmaf(t,t,var); }
    var*=(1.f/NN);
    float rsn=rsqrtf(var+LN_EPS);
    float outv[30];
#pragma unroll
    for (int l=0;l<NN;l++){
        float v=(a[l]-mean)*rsn*__ldg(&ln2w[l])+__ldg(&ln2b[l]);
        v=fmaxf(v,0.f);
        outv[l]=v+d[l];
    }
    __syncthreads();   // all reads of base done
#pragma unroll
    for (int l=0;l<NN;l++) base[c*NN+l]=outv[l];   // compact stage in front region
    __syncthreads();
    for (int i=tid;i<7680;i+=256) g_z[b*7680+i]=base[i];
}

// ---------------- tiled SGEMM: C[M,N] = act(A[M,K] @ W[N,K]^T + bias) ----------------
__global__ void __launch_bounds__(256) gemm_kernel(const float* __restrict__ A,
                                                   const float* __restrict__ W,
                                                   const float* __restrict__ bias,
                                                   float* __restrict__ C,
                                                   int M, int N, int K, int relu)
{
    __shared__ float sA[64][17];
    __shared__ float sW[64][17];
    const int tid=threadIdx.x;
    const int m0=blockIdx.y*64, n0=blockIdx.x*64;
    const int tr=(tid/16)*4, tc=(tid%16)*4;
    float acc[4][4];
#pragma unroll
    for (int i=0;i<4;i++)
#pragma unroll
        for (int j=0;j<4;j++) acc[i][j]=0.f;

    for (int k0=0;k0<K;k0+=16){
        for (int i=tid;i<1024;i+=256){
            int k=i&15, r=i>>4;
            int gm=m0+r, gk=k0+k;
            sA[r][k]=(gm<M && gk<K)? A[gm*K+gk] : 0.f;
            int gn=n0+r;
            sW[r][k]=(gn<N && gk<K)? W[gn*K+gk] : 0.f;
        }
        __syncthreads();
#pragma unroll
        for (int k=0;k<16;k++){
            float a[4], w[4];
#pragma unroll
            for (int i=0;i<4;i++) a[i]=sA[tr+i][k];
#pragma unroll
            for (int j=0;j<4;j++) w[j]=sW[tc+j][k];
#pragma unroll
            for (int i=0;i<4;i++)
#pragma unroll
                for (int j=0;j<4;j++) acc[i][j]=fmaf(a[i],w[j],acc[i][j]);
        }
        __syncthreads();
    }
#pragma unroll
    for (int i=0;i<4;i++){
        int gm=m0+tr+i;
        if (gm>=M) continue;
#pragma unroll
        for (int j=0;j<4;j++){
            int gn=n0+tc+j;
            if (gn>=N) continue;
            float v=acc[i][j]+bias[gn];
            if (relu) v=fmaxf(v,0.f);
            C[gm*N+gn]=v;
        }
    }
}

// ---------------- ei output ----------------
__global__ void ei_kernel(const int* __restrict__ eidx, float* __restrict__ out)
{
    int e=blockIdx.x*blockDim.x+threadIdx.x;
    if (e>=ET) return;
    int s,d;
    if (e<NE){ s=eidx[e]; d=eidx[NE+e]; }
    else { s=e-NE; d=e-NE; }
    out[EI_OFF+e]      =(float)s;
    out[EI_OFF+ET+e]   =(float)d;
}

// ---------------- launch ----------------
extern "C" void kernel_launch(void* const* d_in, const int* in_sizes, int n_in,
                              void* d_out, int out_size)
{
    const float* x      =(const float*)d_in[0];
    const float* gat_Wl =(const float*)d_in[1];
    const float* gat_bl =(const float*)d_in[2];
    const float* gat_Wr =(const float*)d_in[3];
    const float* gat_br =(const float*)d_in[4];
    const float* gat_att=(const float*)d_in[5];
    const float* gat_bias=(const float*)d_in[6];
    const float* tcn0_w =(const float*)d_in[7];
    const float* tcn0_b =(const float*)d_in[8];
    const float* ln0_w  =(const float*)d_in[9];
    const float* ln0_b  =(const float*)d_in[10];
    const float* tcn1_w =(const float*)d_in[11];
    const float* tcn1_b =(const float*)d_in[12];
    const float* ln1_w  =(const float*)d_in[13];
    const float* ln1_b  =(const float*)d_in[14];
    const float* ds1_w  =(const float*)d_in[15];
    const float* ds1_b  =(const float*)d_in[16];
    const float* tcn2_w =(const float*)d_in[17];
    const float* tcn2_b =(const float*)d_in[18];
    const float* ln2_w  =(const float*)d_in[19];
    const float* ln2_b  =(const float*)d_in[20];
    const float* ds2_w  =(const float*)d_in[21];
    const float* ds2_b  =(const float*)d_in[22];
    const float* fc1_w  =(const float*)d_in[23];
    const float* fc1_b  =(const float*)d_in[24];
    const float* fc2_w  =(const float*)d_in[25];
    const float* fc2_b  =(const float*)d_in[26];
    const float* fc3_w  =(const float*)d_in[27];
    const float* fc3_b  =(const float*)d_in[28];
    const int*   edge   =(const int*)d_in[29];
    float* out=(float*)d_out;

    cudaFuncSetAttribute(attn_kernel, cudaFuncAttributeMaxDynamicSharedMemorySize, ATTN_SMEM_BYTES);
    cudaFuncSetAttribute(tcn0_kernel, cudaFuncAttributeMaxDynamicSharedMemorySize, L0_SMEM);
    cudaFuncSetAttribute(tcn1_kernel, cudaFuncAttributeMaxDynamicSharedMemorySize, L1_SMEM);
    cudaFuncSetAttribute(tcn2_kernel, cudaFuncAttributeMaxDynamicSharedMemorySize, L2_SMEM);

    prep_kernel<<<512,256>>>(gat_Wl, gat_Wr, tcn0_w, tcn1_w, tcn2_w, ds1_w, ds2_w);
    xform_kernel<<<NL/32,256>>>(x, gat_bl, gat_br);

    int write_alpha = (out_size >= ALPHA_OFF + ALPHA_LEN) ? 1 : 0;
    attn_kernel<<<NB,256,ATTN_SMEM_BYTES>>>(edge, gat_att, gat_bias, out, write_alpha);

    tcn0_kernel<<<NB,256,L0_SMEM>>>(tcn0_b, ln0_w, ln0_b);
    tcn1_kernel<<<NB,256,L1_SMEM>>>(tcn1_b, ln1_w, ln1_b, ds1_b);
    tcn2_kernel<<<NB,256,L2_SMEM>>>(tcn2_b, ln2_w, ln2_b, ds2_b);

    void *pz=nullptr,*pz1=nullptr,*pz2=nullptr;
    cudaGetSymbolAddress(&pz,  g_z);
    cudaGetSymbolAddress(&pz1, g_z1);
    cudaGetSymbolAddress(&pz2, g_z2);

    gemm_kernel<<<dim3(512/64, NB/64),256>>>((const float*)pz,  fc1_w, fc1_b, (float*)pz1, NB, 512, 7680, 1);
    gemm_kernel<<<dim3(256/64, NB/64),256>>>((const float*)pz1, fc2_w, fc2_b, (float*)pz2, NB, 256, 512, 1);
    gemm_kernel<<<dim3((144+63)/64, NB/64),256>>>((const float*)pz2, fc3_w, fc3_b, out, NB, 144, 256, 0);

    if (out_size >= EI_OFF + EI_LEN)
        ei_kernel<<<(ET+255)/256,256>>>(edge, out);
}

// round 3
// speedup vs baseline: 2.1701x; 1.4589x over previous
#include <cuda_runtime.h>
#include <cuda_bf16.h>

// ---------------- problem constants ----------------
#define NN   30
#define HH   4
#define CC   64
#define HC   256
#define FIN  64
#define NB   1024
#define EPG  240
#define NE   (NB*EPG)
#define NL   (NB*NN)
#define ET   (NE+NL)
#define EG   (EPG+NN)

#define OUT_LEN   (NB*144)
#define ALPHA_OFF OUT_LEN
#define ALPHA_LEN (ET*HH)
#define EI_OFF    (ALPHA_OFF+ALPHA_LEN)
#define EI_LEN    (2*ET)

#define LN_EPS 1e-5f
#define NSLOPE 0.2f

// padded activation row: [4 zero][30 data][6 zero] = 40 floats
#define RS 40

typedef unsigned long long u64;

__device__ __forceinline__ u64 pk2(float a, float b){
    u64 r; asm("mov.b64 %0,{%1,%2};":"=l"(r):"f"(a),"f"(b)); return r;
}
__device__ __forceinline__ u64 f2fma(u64 a, u64 b, u64 c){
    u64 d; asm("fma.rn.f32x2 %0,%1,%2,%3;":"=l"(d):"l"(a),"l"(b),"l"(c)); return d;
}
__device__ __forceinline__ void upk(u64 v, float& lo, float& hi){
    asm("mov.b64 {%0,%1},%2;":"=f"(lo),"=f"(hi):"l"(v));
}

// ---------------- device scratch (static, no allocation) ----------------
__device__ float g_WlT[FIN*HC];
__device__ float g_WrT[FIN*HC];
// packed conv weights: [(cin)*Cout + c]*4 = {w0,w1,w2,wd}; +1 pad row for prefetch
__device__ float g_w0p[257*256*4];
__device__ float g_w1p[257*512*4];
__device__ float g_w2p[513*256*4];
__device__ float g_xl[NL*HC];
__device__ float g_xr[NL*HC];
__device__ float g_h [NB*HC*NN];
__device__ float g_y0[NB*256*RS];
__device__ float g_y1[NB*512*RS];
__device__ float g_z [NB*HC*NN];
__device__ float g_z1[NB*512];
__device__ float g_z2[NB*256];
#define SK 4
__device__ float g_p1[SK*1024*512];

// ---------------- weight transposes / packing ----------------
__global__ void prep_kernel(const float* __restrict__ Wl, const float* __restrict__ Wr,
                            const float* __restrict__ w0, const float* __restrict__ w1,
                            const float* __restrict__ w2, const float* __restrict__ d1,
                            const float* __restrict__ d2)
{
    int t0 = blockIdx.x*blockDim.x + threadIdx.x;
    int stride = gridDim.x*blockDim.x;
    for (int i=t0;i<FIN*HC;i+=stride){ int j=i%HC,k=i/HC; g_WlT[i]=Wl[j*FIN+k]; g_WrT[i]=Wr[j*FIN+k]; }
    for (int i=t0;i<257*256*4;i+=stride){
        int t=i&3, c=(i>>2)&255, cin=i>>10;
        float v=0.f;
        if (cin<256 && t<3) v=w0[(c*256+cin)*3+t];
        g_w0p[i]=v;
    }
    for (int i=t0;i<257*512*4;i+=stride){
        int t=i&3, c=(i>>2)&511, cin=i>>11;
        float v=0.f;
        if (cin<256){ v = (t<3)? w1[(c*256+cin)*3+t] : d1[c*256+cin]; }
        g_w1p[i]=v;
    }
    for (int i=t0;i<513*256*4;i+=stride){
        int t=i&3, c=(i>>2)&255, cin=i>>10;
        float v=0.f;
        if (cin<512){ v = (t<3)? w2[(c*512+cin)*3+t] : d2[c*512+cin]; }
        g_w2p[i]=v;
    }
}

// ---------------- xl = x@Wl^T+bl, xr = x@Wr^T+br ----------------
__global__ void __launch_bounds__(256) xform_kernel(const float* __restrict__ x,
                                                    const float* __restrict__ bl,
                                                    const float* __restrict__ br)
{
    __shared__ float xs[32*FIN];
    const int base = blockIdx.x*32;
    const int tid = threadIdx.x;
    for (int i=tid;i<32*FIN;i+=256) xs[i]=x[base*FIN+i];
    __syncthreads();
    float accl[32], accr[32];
#pragma unroll
    for (int n=0;n<32;n++){ accl[n]=0.f; accr[n]=0.f; }
    const int j = tid;
    for (int k=0;k<FIN;k++){
        float wl=g_WlT[k*HC+j], wr=g_WrT[k*HC+j];
#pragma unroll
        for (int n=0;n<32;n++){ float xv=xs[n*FIN+k]; accl[n]=fmaf(wl,xv,accl[n]); accr[n]=fmaf(wr,xv,accr[n]); }
    }
    float blv=bl[j], brv=br[j];
#pragma unroll
    for (int n=0;n<32;n++){
        g_xl[(base+n)*HC+j]=accl[n]+blv;
        g_xr[(base+n)*HC+j]=accr[n]+brv;
    }
}

// ---------------- GATv2 attention: one CTA per graph ----------------
#define ATTN_SMEM_BYTES (18272*4 + 901*4 + 16)

__global__ void __launch_bounds__(256) attn_kernel(const int* __restrict__ eidx,
                                                   const float* __restrict__ att,
                                                   const float* __restrict__ gbias,
                                                   float* __restrict__ out,
                                                   int write_alpha)
{
    extern __shared__ char smemraw[];
    float* xl_s   = (float*)smemraw;
    float* xr_s   = xl_s + 7680;
    float* att_s  = xr_s + 7680;
    float* bias_s = att_s + 256;
    float* esc    = bias_s + 256;
    float* alp    = esc + 1080;
    float* mmax   = alp + 1080;
    float* ssum   = mmax + 120;
    int*   srcl   = (int*)(ssum + 120);
    int*   dstl   = srcl + 270;
    int*   deg    = dstl + 270;
    int*   off    = deg + 30;
    int*   pos    = off + 31;
    int*   order  = pos + 30;

    const int b = blockIdx.x, tid = threadIdx.x;

    for (int i=tid;i<7680;i+=256){ xl_s[i]=g_xl[b*7680+i]; xr_s[i]=g_xr[b*7680+i]; }
    for (int i=tid;i<256;i+=256){ att_s[i]=att[i]; bias_s[i]=gbias[i]; }
    if (tid<30) deg[tid]=0;
    __syncthreads();

    for (int e=tid;e<EG;e+=256){
        int s,d;
        if (e<EPG){ s=eidx[b*EPG+e]-b*NN; d=eidx[NE+b*EPG+e]-b*NN; }
        else      { s=e-EPG; d=e-EPG; }
        srcl[e]=s; dstl[e]=d;
        atomicAdd(&deg[d],1);
    }
    __syncthreads();
    if (tid==0){ off[0]=0; for (int n=0;n<NN;n++) off[n+1]=off[n]+deg[n]; }
    __syncthreads();
    if (tid<30) pos[tid]=off[tid];
    __syncthreads();
    for (int e=tid;e<EG;e+=256){ int slot=atomicAdd(&pos[dstl[e]],1); order[slot]=e; }
    __syncthreads();

    for (int idx=tid; idx<EG*HH; idx+=256){
        int e=idx>>2, h=idx&3;
        const float* ps=&xl_s[srcl[e]*HC + h*CC];
        const float* pd=&xr_s[dstl[e]*HC + h*CC];
        const float* pa=&att_s[h*CC];
        float acc=0.f;
#pragma unroll 8
        for (int c=0;c<CC;c++){
            float v=ps[c]+pd[c];
            v = v>0.f ? v : NSLOPE*v;
            acc = fmaf(v, pa[c], acc);
        }
        esc[e*HH+h]=acc;
    }
    __syncthreads();

    for (int idx=tid; idx<NN*HH; idx+=256){
        int n=idx>>2, h=idx&3;
        float m=-1e30f;
        for (int i=off[n];i<off[n+1];i++) m=fmaxf(m, esc[order[i]*HH+h]);
        float s=0.f;
        for (int i=off[n];i<off[n+1];i++) s+=__expf(esc[order[i]*HH+h]-m);
        mmax[idx]=m; ssum[idx]=s;
    }
    __syncthreads();

    for (int idx=tid; idx<EG*HH; idx+=256){
        int e=idx>>2, h=idx&3;
        int d=dstl[e];
        float a=__expf(esc[e*HH+h]-mmax[d*HH+h])/ssum[d*HH+h];
        alp[e*HH+h]=a;
        if (write_alpha){
            int gid = (e<EPG) ? (b*EPG+e) : (NE + b*NN + (e-EPG));
            out[ALPHA_OFF + gid*HH + h]=a;
        }
    }
    __syncthreads();

    {
        const int j = tid;
        const int h = j>>6;
        for (int n=0;n<NN;n++){
            float acc=0.f;
            for (int i=off[n];i<off[n+1];i++){
                int e=order[i];
                acc = fmaf(alp[e*HH+h], xl_s[srcl[e]*HC+j], acc);
            }
            float v=acc+bias_s[j];
            xr_s[j*NN+n]=fmaxf(v,0.f);
        }
    }
    __syncthreads();
    for (int i=tid;i<7680;i+=256) g_h[b*7680+i]=xr_s[i];
}

// ================= TCN layer 0: conv k3 d1 + LN + relu + residual =================
#define L0_SMEM (256*RS*4)
__global__ void __launch_bounds__(256,2) tcn0_kernel(const float* __restrict__ b0,
    const float* __restrict__ ln0w, const float* __restrict__ ln0b)
{
    extern __shared__ float sm[];
    float* base = sm;             // 256*RS
    const int b = blockIdx.x, tid = threadIdx.x;

    for (int i=tid;i<256*RS;i+=256) base[i]=0.f;
    __syncthreads();
    for (int i=tid;i<7680;i+=256){
        int c=i/NN, l=i-c*NN;
        base[c*RS+4+l]=g_h[b*7680+i];
    }
    __syncthreads();

    const int c = tid;
    u64 acc[15];
    {
        float bb=b0[c]; u64 bp=pk2(bb,bb);
#pragma unroll
        for (int i=0;i<15;i++) acc[i]=bp;
    }
    const float4* wt = (const float4*)g_w0p;
    float4 w = wt[c];
    for (int cin=0;cin<256;cin++){
        float4 wn = wt[(cin+1)*256 + c];          // prefetch next
        const float2* r = (const float2*)&base[cin*RS+2];   // r[0] = E_{-1}
        float2 e[17];
#pragma unroll
        for (int j=0;j<17;j++) e[j]=r[j];
        u64 w0p=pk2(w.x,w.x), w1p=pk2(w.y,w.y), w2p=pk2(w.z,w.z);
        u64 od[16];
#pragma unroll
        for (int j=0;j<16;j++) od[j]=pk2(e[j].y, e[j+1].x);
#pragma unroll
        for (int i=0;i<15;i++){
            acc[i]=f2fma(w1p, pk2(e[i+1].x,e[i+1].y), acc[i]);
            acc[i]=f2fma(w0p, od[i],   acc[i]);
            acc[i]=f2fma(w2p, od[i+1], acc[i]);
        }
        w=wn;
    }
    float a[30];
#pragma unroll
    for (int i=0;i<15;i++) upk(acc[i], a[2*i], a[2*i+1]);
    float mean=0.f;
#pragma unroll
    for (int l=0;l<NN;l++) mean+=a[l];
    mean*=(1.f/NN);
    float var=0.f;
#pragma unroll
    for (int l=0;l<NN;l++){ float d=a[l]-mean; var=fmaf(d,d,var); }
    var*=(1.f/NN);
    float rs=rsqrtf(var+LN_EPS);
    float outv[30];
#pragma unroll
    for (int l=0;l<NN;l++){
        float v=(a[l]-mean)*rs*__ldg(&ln0w[l])+__ldg(&ln0b[l]);
        v=fmaxf(v,0.f);
        outv[l]=v + base[c*RS+4+l];
    }
    __syncthreads();
#pragma unroll
    for (int l=0;l<NN;l++) base[c*RS+4+l]=outv[l];
    __syncthreads();
    for (int i=tid;i<256*RS;i+=256) g_y0[b*256*RS+i]=base[i];
}

// ================= TCN layer 1: conv k3 d2 (512 out) + LN + relu + ds1 =================
#define L1_SMEM (2*256*RS*4)
__global__ void __launch_bounds__(256,2) tcn1_kernel(const float* __restrict__ b1,
    const float* __restrict__ ln1w, const float* __restrict__ ln1b,
    const float* __restrict__ db1)
{
    extern __shared__ float sm[];
    float* base  = sm;            // 256*RS
    float* stage = sm + 256*RS;   // 256*RS
    const int b = blockIdx.x, tid = threadIdx.x;

    for (int i=tid;i<256*RS;i+=256){ base[i]=g_y0[b*256*RS+i]; stage[i]=0.f; }
    __syncthreads();

    const float4* wt = (const float4*)g_w1p;
    for (int pass=0;pass<2;pass++){
        const int c = tid + pass*256;
        u64 acc[15], ad[15];
        {
            float bb=b1[c], bd=db1[c];
            u64 p1=pk2(bb,bb), p2=pk2(bd,bd);
#pragma unroll
            for (int i=0;i<15;i++){ acc[i]=p1; ad[i]=p2; }
        }
        float4 w = wt[c];
        for (int cin=0;cin<256;cin++){
            float4 wn = wt[(cin+1)*512 + c];
            const float* r=&base[cin*RS];
            u64 w0p=pk2(w.x,w.x), w1p=pk2(w.y,w.y), w2p=pk2(w.z,w.z), wdp=pk2(w.w,w.w);
            u64 bp[17];
#pragma unroll
            for (int j=0;j<17;j++) bp[j]=*(const u64*)(r+2+2*j);
#pragma unroll
            for (int i=0;i<15;i++){
                acc[i]=f2fma(w0p,bp[i],  acc[i]);
                acc[i]=f2fma(w1p,bp[i+1],acc[i]);
                acc[i]=f2fma(w2p,bp[i+2],acc[i]);
                ad [i]=f2fma(wdp,bp[i+1],ad [i]);
            }
            w=wn;
        }
        float a[30], d[30];
#pragma unroll
        for (int i=0;i<15;i++){ upk(acc[i],a[2*i],a[2*i+1]); upk(ad[i],d[2*i],d[2*i+1]); }
        float mean=0.f;
#pragma unroll
        for (int l=0;l<NN;l++) mean+=a[l];
        mean*=(1.f/NN);
        float var=0.f;
#pragma unroll
        for (int l=0;l<NN;l++){ float t=a[l]-mean; var=fmaf(t,t,var); }
        var*=(1.f/NN);
        float rsn=rsqrtf(var+LN_EPS);
#pragma unroll
        for (int l=0;l<NN;l++){
            float v=(a[l]-mean)*rsn*__ldg(&ln1w[l])+__ldg(&ln1b[l]);
            v=fmaxf(v,0.f);
            stage[tid*RS+4+l]=v+d[l];
        }
        __syncthreads();
        for (int i=tid;i<256*RS;i+=256) g_y1[b*512*RS + pass*256*RS + i]=stage[i];
        __syncthreads();
    }
}

// ================= TCN layer 2: conv k3 d4 (256 out, 512 in) + LN + relu + ds2 =================
#define L2_SMEM (512*RS*4)
__global__ void __launch_bounds__(256,2) tcn2_kernel(const float* __restrict__ b2,
    const float* __restrict__ ln2w, const float* __restrict__ ln2b,
    const float* __restrict__ db2)
{
    extern __shared__ float sm[];
    float* base = sm;    // 512*RS
    const int b = blockIdx.x, tid = threadIdx.x;

    for (int i=tid;i<512*RS;i+=256) base[i]=g_y1[b*512*RS+i];
    __syncthreads();

    const int c = tid;
    u64 acc[15], ad[15];
    {
        float bb=b2[c], bd=db2[c];
        u64 p1=pk2(bb,bb), p2=pk2(bd,bd);
#pragma unroll
        for (int i=0;i<15;i++){ acc[i]=p1; ad[i]=p2; }
    }
    const float4* wt = (const float4*)g_w2p;
    float4 w = wt[c];
    for (int cin=0;cin<512;cin++){
        float4 wn = wt[(cin+1)*256 + c];
        const float* r=&base[cin*RS];
        u64 w0p=pk2(w.x,w.x), w1p=pk2(w.y,w.y), w2p=pk2(w.z,w.z), wdp=pk2(w.w,w.w);
        u64 bp[19];
#pragma unroll
        for (int j=0;j<19;j++) bp[j]=*(const u64*)(r+2*j);
#pragma unroll
        for (int i=0;i<15;i++){
            acc[i]=f2fma(w0p,bp[i],  acc[i]);
            acc[i]=f2fma(w1p,bp[i+2],acc[i]);
            acc[i]=f2fma(w2p,bp[i+4],acc[i]);
            ad [i]=f2fma(wdp,bp[i+2],ad [i]);
        }
        w=wn;
    }
    float a[30], d[30];
#pragma unroll
    for (int i=0;i<15;i++){ upk(acc[i],a[2*i],a[2*i+1]); upk(ad[i],d[2*i],d[2*i+1]); }
    float mean=0.f;
#pragma unroll
    for (int l=0;l<NN;l++) mean+=a[l];
    mean*=(1.f/NN);
    float var=0.f;
#pragma unroll
    for (int l=0;l<NN;l++){ float t=a[l]-mean; var=fmaf(t,t,var); }
    var*=(1.f/NN);
    float rsn=rsqrtf(var+LN_EPS);
    float outv[30];
#pragma unroll
    for (int l=0;l<NN;l++){
        float v=(a[l]-mean)*rsn*__ldg(&ln2w[l])+__ldg(&ln2b[l]);
        v=fmaxf(v,0.f);
        outv[l]=v+d[l];
    }
    __syncthreads();
#pragma unroll
    for (int l=0;l<NN;l++) base[c*NN+l]=outv[l];
    __syncthreads();
    for (int i=tid;i<7680;i+=256) g_z[b*7680+i]=base[i];
}

// ================= fc1: split-K f32x2 GEMM, tile 128x64, thread 8x4 =================
__global__ void __launch_bounds__(256,2) fc1_kernel(const float* __restrict__ A,
                                                    const float* __restrict__ W)
{
    __shared__ float2 sA[128][17];
    __shared__ float2 sW[64][17];
    const int tid=threadIdx.x;
    const int n0=blockIdx.x*64, m0=blockIdx.y*128, kz=blockIdx.z;
    const int ty=tid>>4, tx=tid&15;
    u64 acc[8][4];
    u64 z=pk2(0.f,0.f);
#pragma unroll
    for (int i=0;i<8;i++)
#pragma unroll
        for (int j=0;j<4;j++) acc[i][j]=z;

    const int kbase = kz*(7680/SK);
    for (int k0=0;k0<7680/SK;k0+=32){
#pragma unroll
        for (int q=0;q<4;q++){
            int idx=tid+q*256; int m=idx>>3, kq=idx&7;
            float4 v=*(const float4*)&A[(m0+m)*7680 + kbase+k0+4*kq];
            sA[m][2*kq]  =make_float2(v.x,v.y);
            sA[m][2*kq+1]=make_float2(v.z,v.w);
        }
#pragma unroll
        for (int q=0;q<2;q++){
            int idx=tid+q*256; int m=idx>>3, kq=idx&7;
            float4 v=*(const float4*)&W[(n0+m)*7680 + kbase+k0+4*kq];
            sW[m][2*kq]  =make_float2(v.x,v.y);
            sW[m][2*kq+1]=make_float2(v.z,v.w);
        }
        __syncthreads();
#pragma unroll
        for (int p=0;p<16;p++){
            u64 av[8], wv[4];
#pragma unroll
            for (int i=0;i<8;i++) av[i]=*(const u64*)&sA[ty+16*i][p];
#pragma unroll
            for (int j=0;j<4;j++) wv[j]=*(const u64*)&sW[tx+16*j][p];
#pragma unroll
            for (int i=0;i<8;i++)
#pragma unroll
                for (int j=0;j<4;j++) acc[i][j]=f2fma(av[i],wv[j],acc[i][j]);
        }
        __syncthreads();
    }
#pragma unroll
    for (int i=0;i<8;i++){
        int gm=m0+ty+16*i;
#pragma unroll
        for (int j=0;j<4;j++){
            int gn=n0+tx+16*j;
            float lo,hi; upk(acc[i][j],lo,hi);
            g_p1[(kz*1024+gm)*512+gn]=lo+hi;
        }
    }
}

__global__ void fc1red_kernel(const float* __restrict__ bias)
{
    int i=blockIdx.x*blockDim.x+threadIdx.x;
    float s=g_p1[i]+g_p1[524288+i]+g_p1[2*524288+i]+g_p1[3*524288+i];
    s+=bias[i&511];
    g_z1[i]=fmaxf(s,0.f);
}

// ---------------- tiled SGEMM (fc2/fc3): C = act(A @ W^T + bias) ----------------
__global__ void __launch_bounds__(256) gemm_kernel(const float* __restrict__ A,
                                                   const float* __restrict__ W,
                                                   const float* __restrict__ bias,
                                                   float* __restrict__ C,
                                                   int M, int N, int K, int relu)
{
    __shared__ float sA[64][17];
    __shared__ float sW[64][17];
    const int tid=threadIdx.x;
    const int m0=blockIdx.y*64, n0=blockIdx.x*64;
    const int tr=(tid/16)*4, tc=(tid%16)*4;
    float acc[4][4];
#pragma unroll
    for (int i=0;i<4;i++)
#pragma unroll
        for (int j=0;j<4;j++) acc[i][j]=0.f;

    for (int k0=0;k0<K;k0+=16){
        for (int i=tid;i<1024;i+=256){
            int k=i&15, r=i>>4;
            int gm=m0+r, gk=k0+k;
            sA[r][k]=(gm<M && gk<K)? A[gm*K+gk] : 0.f;
            int gn=n0+r;
            sW[r][k]=(gn<N && gk<K)? W[gn*K+gk] : 0.f;
        }
        __syncthreads();
#pragma unroll
        for (int k=0;k<16;k++){
            float a[4], w[4];
#pragma unroll
            for (int i=0;i<4;i++) a[i]=sA[tr+i][k];
#pragma unroll
            for (int j=0;j<4;j++) w[j]=sW[tc+j][k];
#pragma unroll
            for (int i=0;i<4;i++)
#pragma unroll
                for (int j=0;j<4;j++) acc[i][j]=fmaf(a[i],w[j],acc[i][j]);
        }
        __syncthreads();
    }
#pragma unroll
    for (int i=0;i<4;i++){
        int gm=m0+tr+i;
        if (gm>=M) continue;
#pragma unroll
        for (int j=0;j<4;j++){
            int gn=n0+tc+j;
            if (gn>=N) continue;
            float v=acc[i][j]+bias[gn];
            if (relu) v=fmaxf(v,0.f);
            C[gm*N+gn]=v;
        }
    }
}

// ---------------- ei output ----------------
__global__ void ei_kernel(const int* __restrict__ eidx, float* __restrict__ out)
{
    int e=blockIdx.x*blockDim.x+threadIdx.x;
    if (e>=ET) return;
    int s,d;
    if (e<NE){ s=eidx[e]; d=eidx[NE+e]; }
    else { s=e-NE; d=e-NE; }
    out[EI_OFF+e]      =(float)s;
    out[EI_OFF+ET+e]   =(float)d;
}

// ---------------- launch ----------------
extern "C" void kernel_launch(void* const* d_in, const int* in_sizes, int n_in,
                              void* d_out, int out_size)
{
    const float* x      =(const float*)d_in[0];
    const float* gat_Wl =(const float*)d_in[1];
    const float* gat_bl =(const float*)d_in[2];
    const float* gat_Wr =(const float*)d_in[3];
    const float* gat_br =(const float*)d_in[4];
    const float* gat_att=(const float*)d_in[5];
    const float* gat_bias=(const float*)d_in[6];
    const float* tcn0_w =(const float*)d_in[7];
    const float* tcn0_b =(const float*)d_in[8];
    const float* ln0_w  =(const float*)d_in[9];
    const float* ln0_b  =(const float*)d_in[10];
    const float* tcn1_w =(const float*)d_in[11];
    const float* tcn1_b =(const float*)d_in[12];
    const float* ln1_w  =(const float*)d_in[13];
    const float* ln1_b  =(const float*)d_in[14];
    const float* ds1_w  =(const float*)d_in[15];
    const float* ds1_b  =(const float*)d_in[16];
    const float* tcn2_w =(const float*)d_in[17];
    const float* tcn2_b =(const float*)d_in[18];
    const float* ln2_w  =(const float*)d_in[19];
    const float* ln2_b  =(const float*)d_in[20];
    const float* ds2_w  =(const float*)d_in[21];
    const float* ds2_b  =(const float*)d_in[22];
    const float* fc1_w  =(const float*)d_in[23];
    const float* fc1_b  =(const float*)d_in[24];
    const float* fc2_w  =(const float*)d_in[25];
    const float* fc2_b  =(const float*)d_in[26];
    const float* fc3_w  =(const float*)d_in[27];
    const float* fc3_b  =(const float*)d_in[28];
    const int*   edge   =(const int*)d_in[29];
    float* out=(float*)d_out;

    cudaFuncSetAttribute(attn_kernel, cudaFuncAttributeMaxDynamicSharedMemorySize, ATTN_SMEM_BYTES);
    cudaFuncSetAttribute(tcn0_kernel, cudaFuncAttributeMaxDynamicSharedMemorySize, L0_SMEM);
    cudaFuncSetAttribute(tcn1_kernel, cudaFuncAttributeMaxDynamicSharedMemorySize, L1_SMEM);
    cudaFuncSetAttribute(tcn2_kernel, cudaFuncAttributeMaxDynamicSharedMemorySize, L2_SMEM);

    prep_kernel<<<1024,256>>>(gat_Wl, gat_Wr, tcn0_w, tcn1_w, tcn2_w, ds1_w, ds2_w);
    xform_kernel<<<NL/32,256>>>(x, gat_bl, gat_br);

    int write_alpha = (out_size >= ALPHA_OFF + ALPHA_LEN) ? 1 : 0;
    attn_kernel<<<NB,256,ATTN_SMEM_BYTES>>>(edge, gat_att, gat_bias, out, write_alpha);

    tcn0_kernel<<<NB,256,L0_SMEM>>>(tcn0_b, ln0_w, ln0_b);
    tcn1_kernel<<<NB,256,L1_SMEM>>>(tcn1_b, ln1_w, ln1_b, ds1_b);
    tcn2_kernel<<<NB,256,L2_SMEM>>>(tcn2_b, ln2_w, ln2_b, ds2_b);

    void *pz=nullptr,*pz1=nullptr,*pz2=nullptr;
    cudaGetSymbolAddress(&pz,  g_z);
    cudaGetSymbolAddress(&pz1, g_z1);
    cudaGetSymbolAddress(&pz2, g_z2);

    fc1_kernel<<<dim3(8,8,SK),256>>>((const float*)pz, fc1_w);
    fc1red_kernel<<<(1024*512)/256,256>>>(fc1_b);

    gemm_kernel<<<dim3(256/64, NB/64),256>>>((const float*)pz1, fc2_w, fc2_b, (float*)pz2, NB, 256, 512, 1);
    gemm_kernel<<<dim3((144+63)/64, NB/64),256>>>((const float*)pz2, fc3_w, fc3_b, out, NB, 144, 256, 0);

    if (out_size >= EI_OFF + EI_LEN)
        ei_kernel<<<(ET+255)/256,256>>>(edge, out);
}

// round 4
// speedup vs baseline: 2.1712x; 1.0005x over previous
#include <cuda_runtime.h>
#include <cuda_bf16.h>

// ---------------- problem constants ----------------
#define NN   30
#define HH   4
#define CC   64
#define HC   256
#define FIN  64
#define NB   1024
#define EPG  240
#define NE   (NB*EPG)
#define NL   (NB*NN)
#define ET   (NE+NL)
#define EG   (EPG+NN)

#define OUT_LEN   (NB*144)
#define ALPHA_OFF OUT_LEN
#define ALPHA_LEN (ET*HH)
#define EI_OFF    (ALPHA_OFF+ALPHA_LEN)
#define EI_LEN    (2*ET)

#define LN_EPS 1e-5f
#define NSLOPE 0.2f

// padded activation row: [4 zero][30 data][6 zero] = 40 floats
#define RS 40

typedef unsigned long long u64;

__device__ __forceinline__ u64 pk2(float a, float b){
    u64 r; asm("mov.b64 %0,{%1,%2};":"=l"(r):"f"(a),"f"(b)); return r;
}
__device__ __forceinline__ u64 f2fma(u64 a, u64 b, u64 c){
    u64 d; asm("fma.rn.f32x2 %0,%1,%2,%3;":"=l"(d):"l"(a),"l"(b),"l"(c)); return d;
}
__device__ __forceinline__ void upk(u64 v, float& lo, float& hi){
    asm("mov.b64 {%0,%1},%2;":"=f"(lo),"=f"(hi):"l"(v));
}

// ---------------- device scratch (static, no allocation) ----------------
__device__ float g_WlT[FIN*HC];
__device__ float g_WrT[FIN*HC];
// packed conv weights: [(cin)*Cout + c]*4 = {w0,w1,w2,wd}; +1 pad row for prefetch
__device__ float g_w0p[257*256*4];
__device__ float g_w1p[257*512*4];
__device__ float g_w2p[513*256*4];
__device__ float g_xl[NL*HC];
__device__ float g_xr[NL*HC];
__device__ float g_h [NB*HC*NN];
__device__ float g_y0[NB*256*RS];
__device__ float g_y1[NB*512*RS];
__device__ float g_z [NB*HC*NN];
__device__ float g_z1[NB*512];
__device__ float g_z2[NB*256];
#define SK 4
__device__ float g_p1[SK*1024*512];

// ---------------- weight transposes / packing ----------------
__global__ void prep_kernel(const float* __restrict__ Wl, const float* __restrict__ Wr,
                            const float* __restrict__ w0, const float* __restrict__ w1,
                            const float* __restrict__ w2, const float* __restrict__ d1,
                            const float* __restrict__ d2)
{
    int t0 = blockIdx.x*blockDim.x + threadIdx.x;
    int stride = gridDim.x*blockDim.x;
    for (int i=t0;i<FIN*HC;i+=stride){ int j=i%HC,k=i/HC; g_WlT[i]=Wl[j*FIN+k]; g_WrT[i]=Wr[j*FIN+k]; }
    for (int i=t0;i<257*256*4;i+=stride){
        int t=i&3, c=(i>>2)&255, cin=i>>10;
        float v=0.f;
        if (cin<256 && t<3) v=w0[(c*256+cin)*3+t];
        g_w0p[i]=v;
    }
    for (int i=t0;i<257*512*4;i+=stride){
        int t=i&3, c=(i>>2)&511, cin=i>>11;
        float v=0.f;
        if (cin<256){ v = (t<3)? w1[(c*256+cin)*3+t] : d1[c*256+cin]; }
        g_w1p[i]=v;
    }
    for (int i=t0;i<513*256*4;i+=stride){
        int t=i&3, c=(i>>2)&255, cin=i>>10;
        float v=0.f;
        if (cin<512){ v = (t<3)? w2[(c*512+cin)*3+t] : d2[c*512+cin]; }
        g_w2p[i]=v;
    }
}

// ---------------- xl = x@Wl^T+bl, xr = x@Wr^T+br ----------------
__global__ void __launch_bounds__(256) xform_kernel(const float* __restrict__ x,
                                                    const float* __restrict__ bl,
                                                    const float* __restrict__ br)
{
    __shared__ float xs[32*FIN];
    const int base = blockIdx.x*32;
    const int tid = threadIdx.x;
    for (int i=tid;i<32*FIN;i+=256) xs[i]=x[base*FIN+i];
    __syncthreads();
    float accl[32], accr[32];
#pragma unroll
    for (int n=0;n<32;n++){ accl[n]=0.f; accr[n]=0.f; }
    const int j = tid;
    for (int k=0;k<FIN;k++){
        float wl=g_WlT[k*HC+j], wr=g_WrT[k*HC+j];
#pragma unroll
        for (int n=0;n<32;n++){ float xv=xs[n*FIN+k]; accl[n]=fmaf(wl,xv,accl[n]); accr[n]=fmaf(wr,xv,accr[n]); }
    }
    float blv=bl[j], brv=br[j];
#pragma unroll
    for (int n=0;n<32;n++){
        g_xl[(base+n)*HC+j]=accl[n]+blv;
        g_xr[(base+n)*HC+j]=accr[n]+brv;
    }
}

// ---------------- GATv2 attention: one CTA per graph ----------------
#define ATTN_SMEM_BYTES (18272*4 + 901*4 + 16)

__global__ void __launch_bounds__(256) attn_kernel(const int* __restrict__ eidx,
                                                   const float* __restrict__ att,
                                                   const float* __restrict__ gbias,
                                                   float* __restrict__ out,
                                                   int write_alpha)
{
    extern __shared__ char smemraw[];
    float* xl_s   = (float*)smemraw;
    float* xr_s   = xl_s + 7680;
    float* att_s  = xr_s + 7680;
    float* bias_s = att_s + 256;
    float* esc    = bias_s + 256;
    float* alp    = esc + 1080;
    float* mmax   = alp + 1080;
    float* ssum   = mmax + 120;
    int*   srcl   = (int*)(ssum + 120);
    int*   dstl   = srcl + 270;
    int*   deg    = dstl + 270;
    int*   off    = deg + 30;
    int*   pos    = off + 31;
    int*   order  = pos + 30;

    const int b = blockIdx.x, tid = threadIdx.x;

    for (int i=tid;i<7680;i+=256){ xl_s[i]=g_xl[b*7680+i]; xr_s[i]=g_xr[b*7680+i]; }
    for (int i=tid;i<256;i+=256){ att_s[i]=att[i]; bias_s[i]=gbias[i]; }
    if (tid<30) deg[tid]=0;
    __syncthreads();

    for (int e=tid;e<EG;e+=256){
        int s,d;
        if (e<EPG){ s=eidx[b*EPG+e]-b*NN; d=eidx[NE+b*EPG+e]-b*NN; }
        else      { s=e-EPG; d=e-EPG; }
        srcl[e]=s; dstl[e]=d;
        atomicAdd(&deg[d],1);
    }
    __syncthreads();
    if (tid==0){ off[0]=0; for (int n=0;n<NN;n++) off[n+1]=off[n]+deg[n]; }
    __syncthreads();
    if (tid<30) pos[tid]=off[tid];
    __syncthreads();
    for (int e=tid;e<EG;e+=256){ int slot=atomicAdd(&pos[dstl[e]],1); order[slot]=e; }
    __syncthreads();

    for (int idx=tid; idx<EG*HH; idx+=256){
        int e=idx>>2, h=idx&3;
        const float* ps=&xl_s[srcl[e]*HC + h*CC];
        const float* pd=&xr_s[dstl[e]*HC + h*CC];
        const float* pa=&att_s[h*CC];
        float acc=0.f;
#pragma unroll 8
        for (int c=0;c<CC;c++){
            float v=ps[c]+pd[c];
            v = v>0.f ? v : NSLOPE*v;
            acc = fmaf(v, pa[c], acc);
        }
        esc[e*HH+h]=acc;
    }
    __syncthreads();

    for (int idx=tid; idx<NN*HH; idx+=256){
        int n=idx>>2, h=idx&3;
        float m=-1e30f;
        for (int i=off[n];i<off[n+1];i++) m=fmaxf(m, esc[order[i]*HH+h]);
        float s=0.f;
        for (int i=off[n];i<off[n+1];i++) s+=__expf(esc[order[i]*HH+h]-m);
        mmax[idx]=m; ssum[idx]=s;
    }
    __syncthreads();

    for (int idx=tid; idx<EG*HH; idx+=256){
        int e=idx>>2, h=idx&3;
        int d=dstl[e];
        float a=__expf(esc[e*HH+h]-mmax[d*HH+h])/ssum[d*HH+h];
        alp[e*HH+h]=a;
        if (write_alpha){
            int gid = (e<EPG) ? (b*EPG+e) : (NE + b*NN + (e-EPG));
            out[ALPHA_OFF + gid*HH + h]=a;
        }
    }
    __syncthreads();

    {
        const int j = tid;
        const int h = j>>6;
        for (int n=0;n<NN;n++){
            float acc=0.f;
            for (int i=off[n];i<off[n+1];i++){
                int e=order[i];
                acc = fmaf(alp[e*HH+h], xl_s[srcl[e]*HC+j], acc);
            }
            float v=acc+bias_s[j];
            xr_s[j*NN+n]=fmaxf(v,0.f);
        }
    }
    __syncthreads();
    for (int i=tid;i<7680;i+=256) g_h[b*7680+i]=xr_s[i];
}

// ================= TCN layer 0: conv k3 d1 + LN + relu + residual =================
#define L0_SMEM (256*RS*4)
__global__ void __launch_bounds__(256,2) tcn0_kernel(const float* __restrict__ b0,
    const float* __restrict__ ln0w, const float* __restrict__ ln0b)
{
    extern __shared__ float sm[];
    float* base = sm;             // 256*RS
    const int b = blockIdx.x, tid = threadIdx.x;

    for (int i=tid;i<256*RS;i+=256) base[i]=0.f;
    __syncthreads();
    for (int i=tid;i<7680;i+=256){
        int c=i/NN, l=i-c*NN;
        base[c*RS+4+l]=g_h[b*7680+i];
    }
    __syncthreads();

    const int c = tid;
    u64 acc[15];
    {
        float bb=b0[c]; u64 bp=pk2(bb,bb);
#pragma unroll
        for (int i=0;i<15;i++) acc[i]=bp;
    }
    const float4* wt = (const float4*)g_w0p;
    float4 w = wt[c];
    for (int cin=0;cin<256;cin++){
        float4 wn = wt[(cin+1)*256 + c];          // prefetch next
        const float2* r = (const float2*)&base[cin*RS+2];   // r[0] = E_{-1}
        float2 e[17];
#pragma unroll
        for (int j=0;j<17;j++) e[j]=r[j];
        u64 w0p=pk2(w.x,w.x), w1p=pk2(w.y,w.y), w2p=pk2(w.z,w.z);
        u64 od[16];
#pragma unroll
        for (int j=0;j<16;j++) od[j]=pk2(e[j].y, e[j+1].x);
#pragma unroll
        for (int i=0;i<15;i++){
            acc[i]=f2fma(w1p, pk2(e[i+1].x,e[i+1].y), acc[i]);
            acc[i]=f2fma(w0p, od[i],   acc[i]);
            acc[i]=f2fma(w2p, od[i+1], acc[i]);
        }
        w=wn;
    }
    float a[30];
#pragma unroll
    for (int i=0;i<15;i++) upk(acc[i], a[2*i], a[2*i+1]);
    float mean=0.f;
#pragma unroll
    for (int l=0;l<NN;l++) mean+=a[l];
    mean*=(1.f/NN);
    float var=0.f;
#pragma unroll
    for (int l=0;l<NN;l++){ float d=a[l]-mean; var=fmaf(d,d,var); }
    var*=(1.f/NN);
    float rs=rsqrtf(var+LN_EPS);
    float outv[30];
#pragma unroll
    for (int l=0;l<NN;l++){
        float v=(a[l]-mean)*rs*__ldg(&ln0w[l])+__ldg(&ln0b[l]);
        v=fmaxf(v,0.f);
        outv[l]=v + base[c*RS+4+l];
    }
    __syncthreads();
#pragma unroll
    for (int l=0;l<NN;l++) base[c*RS+4+l]=outv[l];
    __syncthreads();
    for (int i=tid;i<256*RS;i+=256) g_y0[b*256*RS+i]=base[i];
}

// ================= TCN layer 1: conv k3 d2 (512 out) + LN + relu + ds1 =================
#define L1_SMEM (2*256*RS*4)
__global__ void __launch_bounds__(256,2) tcn1_kernel(const float* __restrict__ b1,
    const float* __restrict__ ln1w, const float* __restrict__ ln1b,
    const float* __restrict__ db1)
{
    extern __shared__ float sm[];
    float* base  = sm;            // 256*RS
    float* stage = sm + 256*RS;   // 256*RS
    const int b = blockIdx.x, tid = threadIdx.x;

    for (int i=tid;i<256*RS;i+=256){ base[i]=g_y0[b*256*RS+i]; stage[i]=0.f; }
    __syncthreads();

    const float4* wt = (const float4*)g_w1p;
    for (int pass=0;pass<2;pass++){
        const int c = tid + pass*256;
        u64 acc[15], ad[15];
        {
            float bb=b1[c], bd=db1[c];
            u64 p1=pk2(bb,bb), p2=pk2(bd,bd);
#pragma unroll
            for (int i=0;i<15;i++){ acc[i]=p1; ad[i]=p2; }
        }
        float4 w = wt[c];
        for (int cin=0;cin<256;cin++){
            float4 wn = wt[(cin+1)*512 + c];
            const float* r=&base[cin*RS];
            u64 w0p=pk2(w.x,w.x), w1p=pk2(w.y,w.y), w2p=pk2(w.z,w.z), wdp=pk2(w.w,w.w);
            u64 bp[17];
#pragma unroll
            for (int j=0;j<17;j++) bp[j]=*(const u64*)(r+2+2*j);
#pragma unroll
            for (int i=0;i<15;i++){
                acc[i]=f2fma(w0p,bp[i],  acc[i]);
                acc[i]=f2fma(w1p,bp[i+1],acc[i]);
                acc[i]=f2fma(w2p,bp[i+2],acc[i]);
                ad [i]=f2fma(wdp,bp[i+1],ad [i]);
            }
            w=wn;
        }
        float a[30], d[30];
#pragma unroll
        for (int i=0;i<15;i++){ upk(acc[i],a[2*i],a[2*i+1]); upk(ad[i],d[2*i],d[2*i+1]); }
        float mean=0.f;
#pragma unroll
        for (int l=0;l<NN;l++) mean+=a[l];
        mean*=(1.f/NN);
        float var=0.f;
#pragma unroll
        for (int l=0;l<NN;l++){ float t=a[l]-mean; var=fmaf(t,t,var); }
        var*=(1.f/NN);
        float rsn=rsqrtf(var+LN_EPS);
#pragma unroll
        for (int l=0;l<NN;l++){
            float v=(a[l]-mean)*rsn*__ldg(&ln1w[l])+__ldg(&ln1b[l]);
            v=fmaxf(v,0.f);
            stage[tid*RS+4+l]=v+d[l];
        }
        __syncthreads();
        for (int i=tid;i<256*RS;i+=256) g_y1[b*512*RS + pass*256*RS + i]=stage[i];
        __syncthreads();
    }
}

// ================= TCN layer 2: conv k3 d4 (256 out, 512 in) + LN + relu + ds2 =================
#define L2_SMEM (512*RS*4)
__global__ void __launch_bounds__(256,2) tcn2_kernel(const float* __restrict__ b2,
    const float* __restrict__ ln2w, const float* __restrict__ ln2b,
    const float* __restrict__ db2)
{
    extern __shared__ float sm[];
    float* base = sm;    // 512*RS
    const int b = blockIdx.x, tid = threadIdx.x;

    for (int i=tid;i<512*RS;i+=256) base[i]=g_y1[b*512*RS+i];
    __syncthreads();

    const int c = tid;
    u64 acc[15], ad[15];
    {
        float bb=b2[c], bd=db2[c];
        u64 p1=pk2(bb,bb), p2=pk2(bd,bd);
#pragma unroll
        for (int i=0;i<15;i++){ acc[i]=p1; ad[i]=p2; }
    }
    const float4* wt = (const float4*)g_w2p;
    float4 w = wt[c];
    for (int cin=0;cin<512;cin++){
        float4 wn = wt[(cin+1)*256 + c];
        const float* r=&base[cin*RS];
        u64 w0p=pk2(w.x,w.x), w1p=pk2(w.y,w.y), w2p=pk2(w.z,w.z), wdp=pk2(w.w,w.w);
        u64 bp[19];
#pragma unroll
        for (int j=0;j<19;j++) bp[j]=*(const u64*)(r+2*j);
#pragma unroll
        for (int i=0;i<15;i++){
            acc[i]=f2fma(w0p,bp[i],  acc[i]);
            acc[i]=f2fma(w1p,bp[i+2],acc[i]);
            acc[i]=f2fma(w2p,bp[i+4],acc[i]);
            ad [i]=f2fma(wdp,bp[i+2],ad [i]);
        }
        w=wn;
    }
    float a[30], d[30];
#pragma unroll
    for (int i=0;i<15;i++){ upk(acc[i],a[2*i],a[2*i+1]); upk(ad[i],d[2*i],d[2*i+1]); }
    float mean=0.f;
#pragma unroll
    for (int l=0;l<NN;l++) mean+=a[l];
    mean*=(1.f/NN);
    float var=0.f;
#pragma unroll
    for (int l=0;l<NN;l++){ float t=a[l]-mean; var=fmaf(t,t,var); }
    var*=(1.f/NN);
    float rsn=rsqrtf(var+LN_EPS);
    float outv[30];
#pragma unroll
    for (int l=0;l<NN;l++){
        float v=(a[l]-mean)*rsn*__ldg(&ln2w[l])+__ldg(&ln2b[l]);
        v=fmaxf(v,0.f);
        outv[l]=v+d[l];
    }
    __syncthreads();
#pragma unroll
    for (int l=0;l<NN;l++) base[c*NN+l]=outv[l];
    __syncthreads();
    for (int i=tid;i<7680;i+=256) g_z[b*7680+i]=base[i];
}

// ================= fc1: split-K f32x2 GEMM, tile 128x64, thread 8x4 =================
__global__ void __launch_bounds__(256,2) fc1_kernel(const float* __restrict__ A,
                                                    const float* __restrict__ W)
{
    __shared__ float2 sA[128][17];
    __shared__ float2 sW[64][17];
    const int tid=threadIdx.x;
    const int n0=blockIdx.x*64, m0=blockIdx.y*128, kz=blockIdx.z;
    const int ty=tid>>4, tx=tid&15;
    u64 acc[8][4];
    u64 z=pk2(0.f,0.f);
#pragma unroll
    for (int i=0;i<8;i++)
#pragma unroll
        for (int j=0;j<4;j++) acc[i][j]=z;

    const int kbase = kz*(7680/SK);
    for (int k0=0;k0<7680/SK;k0+=32){
#pragma unroll
        for (int q=0;q<4;q++){
            int idx=tid+q*256; int m=idx>>3, kq=idx&7;
            float4 v=*(const float4*)&A[(m0+m)*7680 + kbase+k0+4*kq];
            sA[m][2*kq]  =make_float2(v.x,v.y);
            sA[m][2*kq+1]=make_float2(v.z,v.w);
        }
#pragma unroll
        for (int q=0;q<2;q++){
            int idx=tid+q*256; int m=idx>>3, kq=idx&7;
            float4 v=*(const float4*)&W[(n0+m)*7680 + kbase+k0+4*kq];
            sW[m][2*kq]  =make_float2(v.x,v.y);
            sW[m][2*kq+1]=make_float2(v.z,v.w);
        }
        __syncthreads();
#pragma unroll
        for (int p=0;p<16;p++){
            u64 av[8], wv[4];
#pragma unroll
            for (int i=0;i<8;i++) av[i]=*(const u64*)&sA[ty+16*i][p];
#pragma unroll
            for (int j=0;j<4;j++) wv[j]=*(const u64*)&sW[tx+16*j][p];
#pragma unroll
            for (int i=0;i<8;i++)
#pragma unroll
                for (int j=0;j<4;j++) acc[i][j]=f2fma(av[i],wv[j],acc[i][j]);
        }
        __syncthreads();
    }
#pragma unroll
    for (int i=0;i<8;i++){
        int gm=m0+ty+16*i;
#pragma unroll
        for (int j=0;j<4;j++){
            int gn=n0+tx+16*j;
            float lo,hi; upk(acc[i][j],lo,hi);
            g_p1[(kz*1024+gm)*512+gn]=lo+hi;
        }
    }
}

__global__ void fc1red_kernel(const float* __restrict__ bias)
{
    int i=blockIdx.x*blockDim.x+threadIdx.x;
    float s=g_p1[i]+g_p1[524288+i]+g_p1[2*524288+i]+g_p1[3*524288+i];
    s+=bias[i&511];
    g_z1[i]=fmaxf(s,0.f);
}

// ---------------- tiled SGEMM (fc2/fc3): C = act(A @ W^T + bias) ----------------
__global__ void __launch_bounds__(256) gemm_kernel(const float* __restrict__ A,
                                                   const float* __restrict__ W,
                                                   const float* __restrict__ bias,
                                                   float* __restrict__ C,
                                                   int M, int N, int K, int relu)
{
    __shared__ float sA[64][17];
    __shared__ float sW[64][17];
    const int tid=threadIdx.x;
    const int m0=blockIdx.y*64, n0=blockIdx.x*64;
    const int tr=(tid/16)*4, tc=(tid%16)*4;
    float acc[4][4];
#pragma unroll
    for (int i=0;i<4;i++)
#pragma unroll
        for (int j=0;j<4;j++) acc[i][j]=0.f;

    for (int k0=0;k0<K;k0+=16){
        for (int i=tid;i<1024;i+=256){
            int k=i&15, r=i>>4;
            int gm=m0+r, gk=k0+k;
            sA[r][k]=(gm<M && gk<K)? A[gm*K+gk] : 0.f;
            int gn=n0+r;
            sW[r][k]=(gn<N && gk<K)? W[gn*K+gk] : 0.f;
        }
        __syncthreads();
#pragma unroll
        for (int k=0;k<16;k++){
            float a[4], w[4];
#pragma unroll
            for (int i=0;i<4;i++) a[i]=sA[tr+i][k];
#pragma unroll
            for (int j=0;j<4;j++) w[j]=sW[tc+j][k];
#pragma unroll
            for (int i=0;i<4;i++)
#pragma unroll
                for (int j=0;j<4;j++) acc[i][j]=fmaf(a[i],w[j],acc[i][j]);
        }
        __syncthreads();
    }
#pragma unroll
    for (int i=0;i<4;i++){
        int gm=m0+tr+i;
        if (gm>=M) continue;
#pragma unroll
        for (int j=0;j<4;j++){
            int gn=n0+tc+j;
            if (gn>=N) continue;
            float v=acc[i][j]+bias[gn];
            if (relu) v=fmaxf(v,0.f);
            C[gm*N+gn]=v;
        }
    }
}

// ---------------- ei output ----------------
__global__ void ei_kernel(const int* __restrict__ eidx, float* __restrict__ out)
{
    int e=blockIdx.x*blockDim.x+threadIdx.x;
    if (e>=ET) return;
    int s,d;
    if (e<NE){ s=eidx[e]; d=eidx[NE+e]; }
    else { s=e-NE; d=e-NE; }
    out[EI_OFF+e]      =(float)s;
    out[EI_OFF+ET+e]   =(float)d;
}

// ---------------- launch ----------------
extern "C" void kernel_launch(void* const* d_in, const int* in_sizes, int n_in,
                              void* d_out, int out_size)
{
    const float* x      =(const float*)d_in[0];
    const float* gat_Wl =(const float*)d_in[1];
    const float* gat_bl =(const float*)d_in[2];
    const float* gat_Wr =(const float*)d_in[3];
    const float* gat_br =(const float*)d_in[4];
    const float* gat_att=(const float*)d_in[5];
    const float* gat_bias=(const float*)d_in[6];
    const float* tcn0_w =(const float*)d_in[7];
    const float* tcn0_b =(const float*)d_in[8];
    const float* ln0_w  =(const float*)d_in[9];
    const float* ln0_b  =(const float*)d_in[10];
    const float* tcn1_w =(const float*)d_in[11];
    const float* tcn1_b =(const float*)d_in[12];
    const float* ln1_w  =(const float*)d_in[13];
    const float* ln1_b  =(const float*)d_in[14];
    const float* ds1_w  =(const float*)d_in[15];
    const float* ds1_b  =(const float*)d_in[16];
    const float* tcn2_w =(const float*)d_in[17];
    const float* tcn2_b =(const float*)d_in[18];
    const float* ln2_w  =(const float*)d_in[19];
    const float* ln2_b  =(const float*)d_in[20];
    const float* ds2_w  =(const float*)d_in[21];
    const float* ds2_b  =(const float*)d_in[22];
    const float* fc1_w  =(const float*)d_in[23];
    const float* fc1_b  =(const float*)d_in[24];
    const float* fc2_w  =(const float*)d_in[25];
    const float* fc2_b  =(const float*)d_in[26];
    const float* fc3_w  =(const float*)d_in[27];
    const float* fc3_b  =(const float*)d_in[28];
    const int*   edge   =(const int*)d_in[29];
    float* out=(float*)d_out;

    cudaFuncSetAttribute(attn_kernel, cudaFuncAttributeMaxDynamicSharedMemorySize, ATTN_SMEM_BYTES);
    cudaFuncSetAttribute(tcn0_kernel, cudaFuncAttributeMaxDynamicSharedMemorySize, L0_SMEM);
    cudaFuncSetAttribute(tcn1_kernel, cudaFuncAttributeMaxDynamicSharedMemorySize, L1_SMEM);
    cudaFuncSetAttribute(tcn2_kernel, cudaFuncAttributeMaxDynamicSharedMemorySize, L2_SMEM);

    prep_kernel<<<1024,256>>>(gat_Wl, gat_Wr, tcn0_w, tcn1_w, tcn2_w, ds1_w, ds2_w);
    xform_kernel<<<NL/32,256>>>(x, gat_bl, gat_br);

    int write_alpha = (out_size >= ALPHA_OFF + ALPHA_LEN) ? 1 : 0;
    attn_kernel<<<NB,256,ATTN_SMEM_BYTES>>>(edge, gat_att, gat_bias, out, write_alpha);

    tcn0_kernel<<<NB,256,L0_SMEM>>>(tcn0_b, ln0_w, ln0_b);
    tcn1_kernel<<<NB,256,L1_SMEM>>>(tcn1_b, ln1_w, ln1_b, ds1_b);
    tcn2_kernel<<<NB,256,L2_SMEM>>>(tcn2_b, ln2_w, ln2_b, ds2_b);

    void *pz=nullptr,*pz1=nullptr,*pz2=nullptr;
    cudaGetSymbolAddress(&pz,  g_z);
    cudaGetSymbolAddress(&pz1, g_z1);
    cudaGetSymbolAddress(&pz2, g_z2);

    fc1_kernel<<<dim3(8,8,SK),256>>>((const float*)pz, fc1_w);
    fc1red_kernel<<<(1024*512)/256,256>>>(fc1_b);

    gemm_kernel<<<dim3(256/64, NB/64),256>>>((const float*)pz1, fc2_w, fc2_b, (float*)pz2, NB, 256, 512, 1);
    gemm_kernel<<<dim3((144+63)/64, NB/64),256>>>((const float*)pz2, fc3_w, fc3_b, out, NB, 144, 256, 0);

    if (out_size >= EI_OFF + EI_LEN)
        ei_kernel<<<(ET+255)/256,256>>>(edge, out);
}

// round 6
// speedup vs baseline: 3.1302x; 1.4417x over previous
#include <cuda_runtime.h>
#include <cuda_bf16.h>
#include <cstdint>

#define NN   30
#define HH   4
#define CC   64
#define HC   256
#define FIN  64
#define NB   1024
#define EPG  240
#define NE   (NB*EPG)
#define NL   (NB*NN)
#define ET   (NE+NL)
#define EG   (EPG+NN)
#define OUT_LEN   (NB*144)
#define ALPHA_OFF OUT_LEN
#define ALPHA_LEN (ET*HH)
#define EI_OFF    (ALPHA_OFF+ALPHA_LEN)
#define EI_LEN    (2*ET)
#define LN_EPS 1e-5f
#define NSLOPE 0.2f
#define RS 40

typedef unsigned long long u64;

__device__ __forceinline__ u64 pk2(float a, float b){
    u64 r; asm("mov.b64 %0,{%1,%2};":"=l"(r):"f"(a),"f"(b)); return r;
}
__device__ __forceinline__ u64 f2fma(u64 a, u64 b, u64 c){
    u64 d; asm("fma.rn.f32x2 %0,%1,%2,%3;":"=l"(d):"l"(a),"l"(b),"l"(c)); return d;
}
__device__ __forceinline__ void upk(u64 v, float& lo, float& hi){
    asm("mov.b64 {%0,%1},%2;":"=f"(lo),"=f"(hi):"l"(v));
}

__device__ __forceinline__ void mma16816(float c[4], uint4 a, uint32_t b0, uint32_t b1){
    asm volatile("mma.sync.aligned.m16n8k16.row.col.f32.bf16.bf16.f32 "
        "{%0,%1,%2,%3},{%4,%5,%6,%7},{%8,%9},{%0,%1,%2,%3};"
        : "+f"(c[0]),"+f"(c[1]),"+f"(c[2]),"+f"(c[3])
        : "r"(a.x),"r"(a.y),"r"(a.z),"r"(a.w),"r"(b0),"r"(b1));
}

// ---------------- device scratch ----------------
__device__ float g_WlT[FIN*HC];
__device__ float g_WrT[FIN*HC];
__device__ float g_xl[NL*HC];
__device__ float g_xr[NL*HC];
__device__ float g_h [(size_t)NB*HC*RS];
__device__ float g_y0[(size_t)NB*256*RS];
__device__ float g_y1[(size_t)NB*512*RS];
__device__ float g_z [NB*HC*NN];
__device__ float g_z1[NB*512];
__device__ float g_z2[NB*256];
#define SK 4
__device__ float g_p1[SK*1024*512];

// A-fragment-packed weights (uint4 = 4 u32 per lane per fragment)
__device__ uint4 g_A0H[24576], g_A0L[24576];   // L0 conv: 48 ksteps * 16 mtiles * 32 lanes
__device__ uint4 g_A1H[49152], g_A1L[49152];   // L1 conv: 48 * 32 * 32
__device__ uint4 g_D1H[16384], g_D1L[16384];   // ds1:     16 * 32 * 32
__device__ uint4 g_A2H[49152], g_A2L[49152];   // L2 conv: 96 * 16 * 32
__device__ uint4 g_D2H[16384], g_D2L[16384];   // ds2:     32 * 16 * 32

__device__ __forceinline__ uint32_t packbf(float v0, float v1, int lo){
    __nv_bfloat16 h0=__float2bfloat16(v0), h1=__float2bfloat16(v1);
    if (lo){ h0=__float2bfloat16(v0-__bfloat162float(h0)); h1=__float2bfloat16(v1-__bfloat162float(h1)); }
    return (uint32_t)__bfloat16_as_ushort(h0) | ((uint32_t)__bfloat16_as_ushort(h1)<<16);
}

__device__ void fill_convA(uint32_t* H, uint32_t* L, const float* w, int Cin, int MT, int nslots,
                           int t0, int stride)
{
    for (int i=t0;i<nslots;i+=stride){
        int q=i&3, lane=(i>>2)&31, mtg=(i>>7)%MT, kstep=i/(MT*128);
        int g=lane>>2, tc=lane&3;
        int m=mtg*16 + g + (q&1)*8;
        int kk=kstep*16 + (q>>1)*8 + tc*2;
        int t=kk/Cin, cin=kk-t*Cin;
        float v0=w[(m*Cin+cin)*3+t], v1=w[(m*Cin+cin+1)*3+t];
        H[i]=packbf(v0,v1,0); L[i]=packbf(v0,v1,1);
    }
}
__device__ void fill_dsA(uint32_t* H, uint32_t* L, const float* w, int Cin, int MT, int nslots,
                         int t0, int stride)
{
    for (int i=t0;i<nslots;i+=stride){
        int q=i&3, lane=(i>>2)&31, mtg=(i>>7)%MT, kstep=i/(MT*128);
        int g=lane>>2, tc=lane&3;
        int m=mtg*16 + g + (q&1)*8;
        int cin=kstep*16 + (q>>1)*8 + tc*2;
        float v0=w[m*Cin+cin], v1=w[m*Cin+cin+1];
        H[i]=packbf(v0,v1,0); L[i]=packbf(v0,v1,1);
    }
}

__global__ void prep_kernel(const float* __restrict__ Wl, const float* __restrict__ Wr,
                            const float* __restrict__ w0, const float* __restrict__ w1,
                            const float* __restrict__ w2, const float* __restrict__ d1,
                            const float* __restrict__ d2)
{
    int t0 = blockIdx.x*blockDim.x + threadIdx.x;
    int stride = gridDim.x*blockDim.x;
    for (int i=t0;i<FIN*HC;i+=stride){ int j=i%HC,k=i/HC; g_WlT[i]=Wl[j*FIN+k]; g_WrT[i]=Wr[j*FIN+k]; }
    fill_convA((uint32_t*)g_A0H,(uint32_t*)g_A0L, w0, 256, 16,  98304, t0, stride);
    fill_convA((uint32_t*)g_A1H,(uint32_t*)g_A1L, w1, 256, 32, 196608, t0, stride);
    fill_convA((uint32_t*)g_A2H,(uint32_t*)g_A2L, w2, 512, 16, 196608, t0, stride);
    fill_dsA  ((uint32_t*)g_D1H,(uint32_t*)g_D1L, d1, 256, 32,  65536, t0, stride);
    fill_dsA  ((uint32_t*)g_D2H,(uint32_t*)g_D2L, d2, 512, 16,  65536, t0, stride);
}

__global__ void __launch_bounds__(256) xform_kernel(const float* __restrict__ x,
                                                    const float* __restrict__ bl,
                                                    const float* __restrict__ br)
{
    __shared__ float xs[32*FIN];
    const int base = blockIdx.x*32;
    const int tid = threadIdx.x;
    for (int i=tid;i<32*FIN;i+=256) xs[i]=x[base*FIN+i];
    __syncthreads();
    float accl[32], accr[32];
#pragma unroll
    for (int n=0;n<32;n++){ accl[n]=0.f; accr[n]=0.f; }
    const int j = tid;
    for (int k=0;k<FIN;k++){
        float wl=g_WlT[k*HC+j], wr=g_WrT[k*HC+j];
#pragma unroll
        for (int n=0;n<32;n++){ float xv=xs[n*FIN+k]; accl[n]=fmaf(wl,xv,accl[n]); accr[n]=fmaf(wr,xv,accr[n]); }
    }
    float blv=bl[j], brv=br[j];
#pragma unroll
    for (int n=0;n<32;n++){
        g_xl[(base+n)*HC+j]=accl[n]+blv;
        g_xr[(base+n)*HC+j]=accr[n]+brv;
    }
}

#define ATTN_SMEM_BYTES (18272*4 + 901*4 + 16)
__global__ void __launch_bounds__(256) attn_kernel(const int* __restrict__ eidx,
                                                   const float* __restrict__ att,
                                                   const float* __restrict__ gbias,
                                                   float* __restrict__ out,
                                                   int write_alpha)
{
    extern __shared__ char smemraw[];
    float* xl_s   = (float*)smemraw;
    float* xr_s   = xl_s + 7680;
    float* att_s  = xr_s + 7680;
    float* bias_s = att_s + 256;
    float* esc    = bias_s + 256;
    float* alp    = esc + 1080;
    float* mmax   = alp + 1080;
    float* ssum   = mmax + 120;
    int*   srcl   = (int*)(ssum + 120);
    int*   dstl   = srcl + 270;
    int*   deg    = dstl + 270;
    int*   off    = deg + 30;
    int*   pos    = off + 31;
    int*   order  = pos + 30;
    const int b = blockIdx.x, tid = threadIdx.x;

    for (int i=tid;i<7680;i+=256){ xl_s[i]=g_xl[b*7680+i]; xr_s[i]=g_xr[b*7680+i]; }
    for (int i=tid;i<256;i+=256){ att_s[i]=att[i]; bias_s[i]=gbias[i]; }
    if (tid<30) deg[tid]=0;
    __syncthreads();
    for (int e=tid;e<EG;e+=256){
        int s,d;
        if (e<EPG){ s=eidx[b*EPG+e]-b*NN; d=eidx[NE+b*EPG+e]-b*NN; }
        else      { s=e-EPG; d=e-EPG; }
        srcl[e]=s; dstl[e]=d;
        atomicAdd(&deg[d],1);
    }
    __syncthreads();
    if (tid==0){ off[0]=0; for (int n=0;n<NN;n++) off[n+1]=off[n]+deg[n]; }
    __syncthreads();
    if (tid<30) pos[tid]=off[tid];
    __syncthreads();
    for (int e=tid;e<EG;e+=256){ int slot=atomicAdd(&pos[dstl[e]],1); order[slot]=e; }
    __syncthreads();
    for (int idx=tid; idx<EG*HH; idx+=256){
        int e=idx>>2, h=idx&3;
        const float* ps=&xl_s[srcl[e]*HC + h*CC];
        const float* pd=&xr_s[dstl[e]*HC + h*CC];
        const float* pa=&att_s[h*CC];
        float acc=0.f;
#pragma unroll 8
        for (int c=0;c<CC;c++){
            float v=ps[c]+pd[c];
            v = v>0.f ? v : NSLOPE*v;
            acc = fmaf(v, pa[c], acc);
        }
        esc[e*HH+h]=acc;
    }
    __syncthreads();
    for (int idx=tid; idx<NN*HH; idx+=256){
        int n=idx>>2, h=idx&3;
        float m=-1e30f;
        for (int i=off[n];i<off[n+1];i++) m=fmaxf(m, esc[order[i]*HH+h]);
        float s=0.f;
        for (int i=off[n];i<off[n+1];i++) s+=__expf(esc[order[i]*HH+h]-m);
        mmax[idx]=m; ssum[idx]=s;
    }
    __syncthreads();
    for (int idx=tid; idx<EG*HH; idx+=256){
        int e=idx>>2, h=idx&3;
        int d=dstl[e];
        float a=__expf(esc[e*HH+h]-mmax[d*HH+h])/ssum[d*HH+h];
        alp[e*HH+h]=a;
        if (write_alpha){
            int gid = (e<EPG) ? (b*EPG+e) : (NE + b*NN + (e-EPG));
            out[ALPHA_OFF + gid*HH + h]=a;
        }
    }
    __syncthreads();
    {
        const int j = tid;
        const int h = j>>6;
        for (int n=0;n<NN;n++){
            float acc=0.f;
            for (int i=off[n];i<off[n+1];i++){
                int e=order[i];
                acc = fmaf(alp[e*HH+h], xl_s[srcl[e]*HC+j], acc);
            }
            float v=acc+bias_s[j];
            xr_s[j*NN+n]=fmaxf(v,0.f);
        }
    }
    __syncthreads();
    for (int i=tid;i<256*RS;i+=256){
        int c=i/RS, col=i-c*RS;
        float v = (col>=4 && col<34) ? xr_s[c*NN + col-4] : 0.f;
        g_h[(size_t)b*256*RS + i]=v;
    }
}

// ================= mma.sync TCN conv layer =================
// CTA = 2 graphs. MODE 0: Cin256->M256 d1 (+res). MODE 1: Cin256->M512 d2 (+ds).
// MODE 2: Cin512->M256 d4 (+ds), compact out.
#define CS 270
#define CONV_SMEM (2*2*40*CS*2)   // hi+lo, 2 graphs, 40 rows of CS bf16 = 86400B

template<int MODE>
__global__ void __launch_bounds__(256,1) conv_mma(
    const float* __restrict__ in,
    const uint4* __restrict__ AH, const uint4* __restrict__ AL,
    const uint4* __restrict__ DH, const uint4* __restrict__ DL,
    const float* __restrict__ db,
    const float* __restrict__ lnw, const float* __restrict__ lnb,
    float* __restrict__ outp)
{
    constexpr int Cin   = (MODE==2)?512:256;
    constexpr int COUT  = (MODE==1)?512:256;
    constexpr int MT    = (MODE==1)?32:16;
    constexpr int MP    = (MODE==1)?2:1;
    constexpr int PH    = (MODE==2)?2:1;
    constexpr int DIL   = (MODE==0)?1:((MODE==1)?2:4);
    constexpr bool HASDS= (MODE>=1);
    constexpr int KS_T  = Cin/16;

    extern __shared__ __nv_bfloat16 sm_bf[];
    __nv_bfloat16* sH = sm_bf;
    __nv_bfloat16* sL = sm_bf + 2*40*CS;
    __shared__ float s_lnw[32], s_lnb[32];

    const int tid=threadIdx.x, lane=tid&31, wid=tid>>5;
    const int g=lane>>2, tc=lane&3;
    const int b0=blockIdx.x*2;

    if (tid<30){ s_lnw[tid]=lnw[tid]; s_lnb[tid]=lnb[tid]; }

    for (int mp=0; mp<MP; mp++){
        float acc[2][8][4];
#pragma unroll
        for (int a=0;a<2;a++)
#pragma unroll
            for (int f=0;f<8;f++)
#pragma unroll
                for (int q=0;q<4;q++) acc[a][f][q]=0.f;
        float dsacc[HASDS?2:1][HASDS?8:1][HASDS?4:1];
        if constexpr(HASDS){
#pragma unroll
            for (int a=0;a<2;a++)
#pragma unroll
                for (int f=0;f<8;f++)
#pragma unroll
                    for (int q=0;q<4;q++) dsacc[a][f][q]=0.f;
        }

        for (int ph=0; ph<PH; ph++){
            if (mp==0){
                if (ph>0) __syncthreads();
                for (int idx=tid; idx<2*256*RS; idx+=256){
                    int gr = idx/(256*RS);
                    int r  = idx - gr*256*RS;
                    int c  = r/RS;
                    int l  = r - c*RS;
                    float v = in[(((size_t)(b0+gr))*Cin + ph*256 + c)*RS + l];
                    __nv_bfloat16 h=__float2bfloat16(v);
                    int sidx=(gr*40+l)*CS+c;
                    sH[sidx]=h;
                    sL[sidx]=__float2bfloat16(v-__bfloat162float(h));
                }
            }
            __syncthreads();

            for (int ch=0; ch<16; ch++){
                const int cin0 = ch*16;
#pragma unroll
                for (int t=0;t<3;t++){
                    const int kstep = t*KS_T + ph*16 + ch;
                    const int abase = (kstep*MT + mp*16 + wid*2)*32 + lane;
                    uint4 ah0=AH[abase], ah1=AH[abase+32];
                    uint4 al0=AL[abase], al1=AL[abase+32];
                    uint4 dh0={0,0,0,0},dh1={0,0,0,0},dl0={0,0,0,0},dl1={0,0,0,0};
                    if constexpr(HASDS){
                        if (t==1){
                            int dbase=((ph*16+ch)*MT + mp*16 + wid*2)*32 + lane;
                            dh0=DH[dbase]; dh1=DH[dbase+32];
                            dl0=DL[dbase]; dl1=DL[dbase+32];
                        }
                    }
                    const int shift = DIL*(t-1);
#pragma unroll
                    for (int f=0; f<8; f++){
                        int n = f*8 + g;
                        int gr = n>>5;
                        int row = gr*40 + (n&31) + 4 + shift;
                        int sidx = row*CS + cin0 + tc*2;
                        uint32_t bh0=*(const uint32_t*)(sH+sidx);
                        uint32_t bh1=*(const uint32_t*)(sH+sidx+8);
                        uint32_t bl0=*(const uint32_t*)(sL+sidx);
                        uint32_t bl1=*(const uint32_t*)(sL+sidx+8);
                        mma16816(acc[0][f], ah0, bh0,bh1);
                        mma16816(acc[1][f], ah1, bh0,bh1);
                        mma16816(acc[0][f], al0, bh0,bh1);
                        mma16816(acc[1][f], al1, bh0,bh1);
                        mma16816(acc[0][f], ah0, bl0,bl1);
                        mma16816(acc[1][f], ah1, bl0,bl1);
                        if constexpr(HASDS){
                            if (t==1){
                                mma16816(dsacc[0][f], dh0, bh0,bh1);
                                mma16816(dsacc[1][f], dh1, bh0,bh1);
                                mma16816(dsacc[0][f], dl0, bh0,bh1);
                                mma16816(dsacc[1][f], dl1, bh0,bh1);
                                mma16816(dsacc[0][f], dh0, bl0,bl1);
                                mma16816(dsacc[1][f], dh1, bl0,bl1);
                            }
                        }
                    }
                }
            }
            if (PH>1) __syncthreads();
        }

        // ---- epilogue ----
#pragma unroll
        for (int mt=0; mt<2; mt++){
            const int mrow0 = mp*256 + wid*32 + mt*16 + g;
#pragma unroll
            for (int half=0; half<2; half++){
                const int mrow = mrow0 + half*8;
                float dbv = 0.f;
                if constexpr(HASDS) dbv = __ldg(&db[mrow]);
#pragma unroll
                for (int gr=0; gr<2; gr++){
                    float s=0.f;
#pragma unroll
                    for (int f=0; f<4; f++)
#pragma unroll
                        for (int i=0;i<2;i++){
                            int l=f*8+tc*2+i;
                            if (l<30) s+=acc[mt][gr*4+f][half*2+i];
                        }
                    s += __shfl_xor_sync(0xffffffffu,s,1);
                    s += __shfl_xor_sync(0xffffffffu,s,2);
                    float mean = s*(1.f/30.f);
                    float qv=0.f;
#pragma unroll
                    for (int f=0; f<4; f++)
#pragma unroll
                        for (int i=0;i<2;i++){
                            int l=f*8+tc*2+i;
                            if (l<30){ float d=acc[mt][gr*4+f][half*2+i]-mean; qv=fmaf(d,d,qv); }
                        }
                    qv += __shfl_xor_sync(0xffffffffu,qv,1);
                    qv += __shfl_xor_sync(0xffffffffu,qv,2);
                    float rsn = rsqrtf(qv*(1.f/30.f)+LN_EPS);

                    size_t rb;
                    if constexpr(MODE==2) rb = (((size_t)(b0+gr))*256 + mrow)*(size_t)NN;
                    else                  rb = (((size_t)(b0+gr))*COUT + mrow)*(size_t)RS;
#pragma unroll
                    for (int f=0; f<4; f++){
                        int l0=f*8+tc*2;
                        if (l0>=30) continue;
                        float o0,o1;
                        {
                            float v=(acc[mt][gr*4+f][half*2+0]-mean)*rsn*s_lnw[l0]+s_lnb[l0];
                            o0=fmaxf(v,0.f);
                            v=(acc[mt][gr*4+f][half*2+1]-mean)*rsn*s_lnw[l0+1]+s_lnb[l0+1];
                            o1=fmaxf(v,0.f);
                        }
                        if constexpr(MODE==0){
                            float2 res=*(const float2*)&in[(((size_t)(b0+gr))*256 + mrow)*RS + 4 + l0];
                            o0+=res.x; o1+=res.y;
                        } else {
                            o0 += dsacc[mt][gr*4+f][half*2+0] + dbv;
                            o1 += dsacc[mt][gr*4+f][half*2+1] + dbv;
                        }
                        if constexpr(MODE==2) *(float2*)&outp[rb+l0]   = make_float2(o0,o1);
                        else                  *(float2*)&outp[rb+4+l0] = make_float2(o0,o1);
                    }
                    if constexpr(MODE!=2){
                        if (tc==0) *(float4*)&outp[rb] = make_float4(0.f,0.f,0.f,0.f);
                        if (tc==3){
                            *(float2*)&outp[rb+34]=make_float2(0.f,0.f);
                            *(float4*)&outp[rb+36]=make_float4(0.f,0.f,0.f,0.f);
                        }
                    }
                }
            }
        }
    }
}

// ================= fc1: split-K f32x2 GEMM =================
__global__ void __launch_bounds__(256,2) fc1_kernel(const float* __restrict__ A,
                                                    const float* __restrict__ W)
{
    __shared__ float2 sA[128][17];
    __shared__ float2 sW[64][17];
    const int tid=threadIdx.x;
    const int n0=blockIdx.x*64, m0=blockIdx.y*128, kz=blockIdx.z;
    const int ty=tid>>4, tx=tid&15;
    u64 acc[8][4];
    u64 z=pk2(0.f,0.f);
#pragma unroll
    for (int i=0;i<8;i++)
#pragma unroll
        for (int j=0;j<4;j++) acc[i][j]=z;
    const int kbase = kz*(7680/SK);
    for (int k0=0;k0<7680/SK;k0+=32){
#pragma unroll
        for (int q=0;q<4;q++){
            int idx=tid+q*256; int m=idx>>3, kq=idx&7;
            float4 v=*(const float4*)&A[(m0+m)*7680 + kbase+k0+4*kq];
            sA[m][2*kq]  =make_float2(v.x,v.y);
            sA[m][2*kq+1]=make_float2(v.z,v.w);
        }
#pragma unroll
        for (int q=0;q<2;q++){
            int idx=tid+q*256; int m=idx>>3, kq=idx&7;
            float4 v=*(const float4*)&W[(n0+m)*7680 + kbase+k0+4*kq];
            sW[m][2*kq]  =make_float2(v.x,v.y);
            sW[m][2*kq+1]=make_float2(v.z,v.w);
        }
        __syncthreads();
#pragma unroll
        for (int p=0;p<16;p++){
            u64 av[8], wv[4];
#pragma unroll
            for (int i=0;i<8;i++) av[i]=*(const u64*)&sA[ty+16*i][p];
#pragma unroll
            for (int j=0;j<4;j++) wv[j]=*(const u64*)&sW[tx+16*j][p];
#pragma unroll
            for (int i=0;i<8;i++)
#pragma unroll
                for (int j=0;j<4;j++) acc[i][j]=f2fma(av[i],wv[j],acc[i][j]);
        }
        __syncthreads();
    }
#pragma unroll
    for (int i=0;i<8;i++){
        int gm=m0+ty+16*i;
#pragma unroll
        for (int j=0;j<4;j++){
            int gn=n0+tx+16*j;
            float lo,hi; upk(acc[i][j],lo,hi);
            g_p1[(kz*1024+gm)*512+gn]=lo+hi;
        }
    }
}

__global__ void fc1red_kernel(const float* __restrict__ bias)
{
    int i=blockIdx.x*blockDim.x+threadIdx.x;
    float s=g_p1[i]+g_p1[524288+i]+g_p1[2*524288+i]+g_p1[3*524288+i];
    s+=bias[i&511];
    g_z1[i]=fmaxf(s,0.f);
}

__global__ void __launch_bounds__(256) gemm_kernel(const float* __restrict__ A,
                                                   const float* __restrict__ W,
                                                   const float* __restrict__ bias,
                                                   float* __restrict__ C,
                                                   int M, int N, int K, int relu)
{
    __shared__ float sA[64][17];
    __shared__ float sW[64][17];
    const int tid=threadIdx.x;
    const int m0=blockIdx.y*64, n0=blockIdx.x*64;
    const int tr=(tid/16)*4, tc=(tid%16)*4;
    float acc[4][4];
#pragma unroll
    for (int i=0;i<4;i++)
#pragma unroll
        for (int j=0;j<4;j++) acc[i][j]=0.f;
    for (int k0=0;k0<K;k0+=16){
        for (int i=tid;i<1024;i+=256){
            int k=i&15, r=i>>4;
            int gm=m0+r, gk=k0+k;
            sA[r][k]=(gm<M && gk<K)? A[gm*K+gk] : 0.f;
            int gn=n0+r;
            sW[r][k]=(gn<N && gk<K)? W[gn*K+gk] : 0.f;
        }
        __syncthreads();
#pragma unroll
        for (int k=0;k<16;k++){
            float a[4], w[4];
#pragma unroll
            for (int i=0;i<4;i++) a[i]=sA[tr+i][k];
#pragma unroll
            for (int j=0;j<4;j++) w[j]=sW[tc+j][k];
#pragma unroll
            for (int i=0;i<4;i++)
#pragma unroll
                for (int j=0;j<4;j++) acc[i][j]=fmaf(a[i],w[j],acc[i][j]);
        }
        __syncthreads();
    }
#pragma unroll
    for (int i=0;i<4;i++){
        int gm=m0+tr+i;
        if (gm>=M) continue;
#pragma unroll
        for (int j=0;j<4;j++){
            int gn=n0+tc+j;
            if (gn>=N) continue;
            float v=acc[i][j]+bias[gn];
            if (relu) v=fmaxf(v,0.f);
            C[gm*N+gn]=v;
        }
    }
}

__global__ void ei_kernel(const int* __restrict__ eidx, float* __restrict__ out)
{
    int e=blockIdx.x*blockDim.x+threadIdx.x;
    if (e>=ET) return;
    int s,d;
    if (e<NE){ s=eidx[e]; d=eidx[NE+e]; }
    else { s=e-NE; d=e-NE; }
    out[EI_OFF+e]    =(float)s;
    out[EI_OFF+ET+e] =(float)d;
}

extern "C" void kernel_launch(void* const* d_in, const int* in_sizes, int n_in,
                              void* d_out, int out_size)
{
    const float* x      =(const float*)d_in[0];
    const float* gat_Wl =(const float*)d_in[1];
    const float* gat_bl =(const float*)d_in[2];
    const float* gat_Wr =(const float*)d_in[3];
    const float* gat_br =(const float*)d_in[4];
    const float* gat_att=(const float*)d_in[5];
    const float* gat_bias=(const float*)d_in[6];
    const float* tcn0_w =(const float*)d_in[7];
    const float* ln0_w  =(const float*)d_in[9];
    const float* ln0_b  =(const float*)d_in[10];
    const float* tcn1_w =(const float*)d_in[11];
    const float* ln1_w  =(const float*)d_in[13];
    const float* ln1_b  =(const float*)d_in[14];
    const float* ds1_w  =(const float*)d_in[15];
    const float* ds1_b  =(const float*)d_in[16];
    const float* tcn2_w =(const float*)d_in[17];
    const float* ln2_w  =(const float*)d_in[19];
    const float* ln2_b  =(const float*)d_in[20];
    const float* ds2_w  =(const float*)d_in[21];
    const float* ds2_b  =(const float*)d_in[22];
    const float* fc1_w  =(const float*)d_in[23];
    const float* fc1_b  =(const float*)d_in[24];
    const float* fc2_w  =(const float*)d_in[25];
    const float* fc2_b  =(const float*)d_in[26];
    const float* fc3_w  =(const float*)d_in[27];
    const float* fc3_b  =(const float*)d_in[28];
    const int*   edge   =(const int*)d_in[29];
    float* out=(float*)d_out;

    cudaFuncSetAttribute(attn_kernel, cudaFuncAttributeMaxDynamicSharedMemorySize, ATTN_SMEM_BYTES);
    cudaFuncSetAttribute(conv_mma<0>, cudaFuncAttributeMaxDynamicSharedMemorySize, CONV_SMEM);
    cudaFuncSetAttribute(conv_mma<1>, cudaFuncAttributeMaxDynamicSharedMemorySize, CONV_SMEM);
    cudaFuncSetAttribute(conv_mma<2>, cudaFuncAttributeMaxDynamicSharedMemorySize, CONV_SMEM);

    prep_kernel<<<1024,256>>>(gat_Wl, gat_Wr, tcn0_w, tcn1_w, tcn2_w, ds1_w, ds2_w);
    xform_kernel<<<NL/32,256>>>(x, gat_bl, gat_br);

    int write_alpha = (out_size >= ALPHA_OFF + ALPHA_LEN) ? 1 : 0;
    attn_kernel<<<NB,256,ATTN_SMEM_BYTES>>>(edge, gat_att, gat_bias, out, write_alpha);

    void *ph=nullptr,*py0=nullptr,*py1=nullptr,*pz=nullptr,*pz1=nullptr,*pz2=nullptr;
    void *a0h,*a0l,*a1h,*a1l,*a2h,*a2l,*d1h,*d1l,*d2h,*d2l;
    cudaGetSymbolAddress(&ph,  g_h);  cudaGetSymbolAddress(&py0, g_y0);
    cudaGetSymbolAddress(&py1, g_y1); cudaGetSymbolAddress(&pz,  g_z);
    cudaGetSymbolAddress(&pz1, g_z1); cudaGetSymbolAddress(&pz2, g_z2);
    cudaGetSymbolAddress(&a0h, g_A0H); cudaGetSymbolAddress(&a0l, g_A0L);
    cudaGetSymbolAddress(&a1h, g_A1H); cudaGetSymbolAddress(&a1l, g_A1L);
    cudaGetSymbolAddress(&a2h, g_A2H); cudaGetSymbolAddress(&a2l, g_A2L);
    cudaGetSymbolAddress(&d1h, g_D1H); cudaGetSymbolAddress(&d1l, g_D1L);
    cudaGetSymbolAddress(&d2h, g_D2H); cudaGetSymbolAddress(&d2l, g_D2L);

    conv_mma<0><<<NB/2,256,CONV_SMEM>>>((const float*)ph,
        (const uint4*)a0h,(const uint4*)a0l,(const uint4*)a0h,(const uint4*)a0l,
        nullptr, ln0_w, ln0_b, (float*)py0);
    conv_mma<1><<<NB/2,256,CONV_SMEM>>>((const float*)py0,
        (const uint4*)a1h,(const uint4*)a1l,(const uint4*)d1h,(const uint4*)d1l,
        ds1_b, ln1_w, ln1_b, (float*)py1);
    conv_mma<2><<<NB/2,256,CONV_SMEM>>>((const float*)py1,
        (const uint4*)a2h,(const uint4*)a2l,(const uint4*)d2h,(const uint4*)d2l,
        ds2_b, ln2_w, ln2_b, (float*)pz);

    fc1_kernel<<<dim3(8,8,SK),256>>>((const float*)pz, fc1_w);
    fc1red_kernel<<<(1024*512)/256,256>>>(fc1_b);

    gemm_kernel<<<dim3(256/64, NB/64),256>>>((const float*)pz1, fc2_w, fc2_b, (float*)pz2, NB, 256, 512, 1);
    gemm_kernel<<<dim3((144+63)/64, NB/64),256>>>((const float*)pz2, fc3_w, fc3_b, out, NB, 144, 256, 0);

    if (out_size >= EI_OFF + EI_LEN)
        ei_kernel<<<(ET+255)/256,256>>>(edge, out);
}